// round 3
// baseline (speedup 1.0000x reference)
#include <cuda_runtime.h>
#include <math.h>

#define CB 128
#define CS 256
#define CT 256
#define CV 512
#define CE 256
#define CH 512
#define CH2 1024
#define CH4 2048

// ---------------- static device scratch ----------------
static __device__ float g_XS[(size_t)CS * CB * CE];
static __device__ float g_DE[(size_t)CT * CB * CE];
static __device__ float g_XP[(size_t)2 * CS * CB * CH4];
static __device__ float g_Y0[(size_t)CS * CB * CH2];
static __device__ float g_ENC[(size_t)CB * CS * CH2];
static __device__ float g_HB[(size_t)2 * 2 * CB * CH];   // [buf][dir][b][j]
static __device__ float g_SC[(size_t)2 * CB * CH];       // [dir][b][j]
static __device__ float g_d0h[(size_t)2 * CH * CB];      // transposed [buf][j][b]
static __device__ float g_d1h[(size_t)2 * CH * CB];
static __device__ float g_d0c[(size_t)CH * CB];
static __device__ float g_d1c[(size_t)CH * CB];
static __device__ float g_ctx[(size_t)CB * CH2];
static __device__ float g_q[(size_t)CB * CH2];
static __device__ float g_b1[CH4];
static __device__ unsigned g_barE;
static __device__ unsigned g_barD;

// ---------------- grid barrier (all blocks resident) ----------------
__device__ __forceinline__ void gbar(unsigned* ctr, unsigned target)
{
    __syncthreads();
    if (threadIdx.x == 0) {
        __threadfence();
        atomicAdd(ctr, 1u);
        volatile unsigned* v = ctr;
        while (*v < target) __nanosleep(64);
    }
    __syncthreads();
}

__device__ __forceinline__ float sigf(float x) { return 1.0f / (1.0f + expf(-x)); }

// ---------------- embedding ----------------
__global__ void embed_k(const float* __restrict__ emb, const int* __restrict__ toks,
                        int L, float* __restrict__ X, long total)
{
    for (long i = (long)blockIdx.x * blockDim.x + threadIdx.x; i < total;
         i += (long)gridDim.x * blockDim.x) {
        int e = (int)(i % CE);
        long r = i / CE;
        int b = (int)(r % CB);
        int t = (int)(r / CB);
        int tok = toks[(long)b * L + t];
        X[i] = (tok == 0) ? 0.0f : emb[(long)tok * CE + e];
    }
}

// ---------------- big precompute GEMM: C = A*W^T + b0 + b1 ----------------
__global__ __launch_bounds__(256) void sgemm_bias(
    int M, int N, int K,
    const float* __restrict__ A, int lda,
    const float* __restrict__ W, int ldw, int woff,
    const float* __restrict__ b0, const float* __restrict__ b1,
    float* __restrict__ C, long long ldc)
{
    __shared__ float As[16][64];
    __shared__ float Ws[16][64];
    const int bm = blockIdx.y * 64, bn = blockIdx.x * 64;
    const int tid = threadIdx.x;
    const int lr = tid >> 2;
    const int lk = (tid & 3) * 4;
    const int tm = (tid >> 4) * 4;
    const int tn = (tid & 15) * 4;

    float acc[4][4] = {};
    for (int k0 = 0; k0 < K; k0 += 16) {
        float4 av = *(const float4*)(A + (size_t)(bm + lr) * lda + k0 + lk);
        float4 wv = *(const float4*)(W + (size_t)(bn + lr) * ldw + woff + k0 + lk);
        As[lk + 0][lr] = av.x; As[lk + 1][lr] = av.y;
        As[lk + 2][lr] = av.z; As[lk + 3][lr] = av.w;
        Ws[lk + 0][lr] = wv.x; Ws[lk + 1][lr] = wv.y;
        Ws[lk + 2][lr] = wv.z; Ws[lk + 3][lr] = wv.w;
        __syncthreads();
#pragma unroll
        for (int kk = 0; kk < 16; kk++) {
            float4 a4 = *(const float4*)&As[kk][tm];
            float4 w4 = *(const float4*)&Ws[kk][tn];
            float ar[4] = {a4.x, a4.y, a4.z, a4.w};
            float wr[4] = {w4.x, w4.y, w4.z, w4.w};
#pragma unroll
            for (int i = 0; i < 4; i++)
#pragma unroll
                for (int j = 0; j < 4; j++)
                    acc[i][j] += ar[i] * wr[j];
        }
        __syncthreads();
    }
#pragma unroll
    for (int i = 0; i < 4; i++) {
        float4 o;
        float* op = (float*)&o;
#pragma unroll
        for (int j = 0; j < 4; j++) {
            int n = bn + tn + j;
            float bv = (b0 ? b0[n] : 0.0f) + (b1 ? b1[n] : 0.0f);
            op[j] = acc[i][j] + bv;
        }
        *(float4*)(C + (long long)(bm + tm + i) * ldc + bn + tn) = o;
    }
}

__global__ void vsum_k(const float* __restrict__ a, const float* __restrict__ b,
                       float* __restrict__ o, int n)
{
    int i = blockIdx.x * blockDim.x + threadIdx.x;
    if (i < n) o[i] = a[i] + b[i];
}

// ---------------- persistent encoder scan (one layer, both dirs) ----------------
// grid (16,4,2) = 128 blocks, 128 threads
__global__ __launch_bounds__(128) void enc_scan(
    int layer, const float* __restrict__ XP, const float* __restrict__ Whh,
    float* __restrict__ HB, float* __restrict__ SC, float* __restrict__ Yout,
    float* __restrict__ DHT, float* __restrict__ DCT, unsigned* __restrict__ bar)
{
    __shared__ float hs[32][33];
    __shared__ float ws[4][32][33];
    const int d = blockIdx.z;
    const int j0 = blockIdx.x * 32, b0 = blockIdx.y * 32;
    const int tid = threadIdx.x;
    const int jj = tid & 7, bb = tid >> 3;
    const float* W_d = Whh + (size_t)d * CH4 * CH;

    for (int t = 0; t < CS; t++) {
        const int td = d ? (CS - 1 - t) : t;
        const float* hin = HB + (size_t)(((t & 1) * 2 + d) * CB) * CH;
        float* hout = HB + (size_t)((((t + 1) & 1) * 2 + d) * CB) * CH;

        float acc[4][2][4] = {};
        for (int k0 = 0; k0 < CH; k0 += 32) {
#pragma unroll
            for (int u = 0; u < 8; u++) {
                int li = tid + 128 * u;
                int k = li & 31, b = li >> 5;
                hs[k][b] = __ldcg(hin + (size_t)(b0 + b) * CH + k0 + k);
            }
#pragma unroll
            for (int u = 0; u < 32; u++) {
                int li = tid + 128 * u;
                int k = li & 31;
                int row = li >> 5;
                int gg2 = row >> 5, j = row & 31;
                ws[gg2][k][j] = W_d[(size_t)(gg2 * CH + j0 + j) * CH + k0 + k];
            }
            __syncthreads();
#pragma unroll
            for (int kk = 0; kk < 32; kk++) {
                float h0v = hs[kk][bb];
                float h1v = hs[kk][bb + 16];
#pragma unroll
                for (int gx = 0; gx < 4; gx++) {
#pragma unroll
                    for (int m = 0; m < 4; m++) {
                        float wv = ws[gx][kk][jj + 8 * m];
                        acc[gx][0][m] += h0v * wv;
                        acc[gx][1][m] += h1v * wv;
                    }
                }
            }
            __syncthreads();
        }
        const float* pre = XP + ((size_t)d * CS + td) * CB * CH4;
#pragma unroll
        for (int bi = 0; bi < 2; bi++) {
            int b = b0 + bb + 16 * bi;
            const float* prow = pre + (size_t)b * CH4;
#pragma unroll
            for (int m = 0; m < 4; m++) {
                int j = j0 + jj + 8 * m;
                float gi = acc[0][bi][m] + prow[j];
                float gf = acc[1][bi][m] + prow[CH + j];
                float gg = acc[2][bi][m] + prow[2 * CH + j];
                float go = acc[3][bi][m] + prow[3 * CH + j];
                size_t ci = (size_t)(d * CB + b) * CH + j;
                float c = sigf(gf) * SC[ci] + sigf(gi) * tanhf(gg);
                SC[ci] = c;
                float h = sigf(go) * tanhf(c);
                hout[(size_t)b * CH + j] = h;
                size_t yi = (layer == 0)
                    ? ((size_t)td * CB + b) * CH2 + (size_t)d * CH + j
                    : ((size_t)b * CS + td) * CH2 + (size_t)d * CH + j;
                Yout[yi] = h;
            }
        }
        gbar(bar, (unsigned)(t + 1) * 128u);
    }
    // epilogue: summed bidirectional final states, transposed [j][b]
    if (d == 0) {
#pragma unroll
        for (int u = 0; u < 8; u++) {
            int li = tid + 128 * u;
            int j = li >> 5, b = li & 31;
            int gj = j0 + j, gb = b0 + b;
            float hf = __ldcg(HB + (size_t)(0 * CB + gb) * CH + gj);          // buf0 dir0
            float hbv = __ldcg(HB + (size_t)(1 * CB + gb) * CH + gj);         // buf0 dir1
            DHT[(size_t)gj * CB + gb] = hf + hbv;
            float cf = __ldcg(SC + (size_t)(0 * CB + gb) * CH + gj);
            float cbv = __ldcg(SC + (size_t)(CB + gb) * CH + gj);
            DCT[(size_t)gj * CB + gb] = cf + cbv;
        }
    }
}

// ---------------- per-block micro-GEMM for decoder phases ----------------
// acc[NR/2] per thread; thread b = tid&127, half = tid>>7 handles rows half*(NR/2)+i.
// AT: A stored transposed [k][128]. rmode 0: row = rbase+ri ; rmode 1: row = (ri>>2)*CH + rbase + (ri&3)
template<int NR, bool AT>
__device__ __forceinline__ void mg(
    float* __restrict__ acc, const float* __restrict__ A, int lda,
    const float* __restrict__ W, int ldw, int woff,
    int rbase, int rmode, int K,
    float* __restrict__ As, float* __restrict__ Ws)
{
    const int tid = threadIdx.x;
    const int b = tid & 127, half = tid >> 7;
    for (int k0 = 0; k0 < K; k0 += 32) {
        if (AT) {
#pragma unroll
            for (int u = 0; u < 16; u++) {
                int idx = tid + 256 * u;
                As[(idx >> 7) * 129 + (idx & 127)] =
                    __ldcg(A + (size_t)(k0 + (idx >> 7)) * 128 + (idx & 127));
            }
        } else {
#pragma unroll
            for (int u = 0; u < 16; u++) {
                int idx = tid + 256 * u;
                As[(idx & 31) * 129 + (idx >> 5)] =
                    __ldcg(A + (size_t)(idx >> 5) * lda + k0 + (idx & 31));
            }
        }
        for (int idx = tid; idx < 32 * NR; idx += 256) {
            int kk = idx & 31, ri = idx >> 5;
            int row = (rmode == 0) ? (rbase + ri)
                                   : ((ri >> 2) * CH + rbase + (ri & 3));
            Ws[kk * NR + ri] = W[(size_t)row * ldw + woff + k0 + kk];
        }
        __syncthreads();
#pragma unroll
        for (int kk = 0; kk < 32; kk++) {
            float a = As[kk * 129 + b];
#pragma unroll
            for (int i = 0; i < NR / 2; i++)
                acc[i] += a * Ws[kk * NR + half * (NR / 2) + i];
        }
        __syncthreads();
    }
}

// ---------------- persistent decoder: all T steps, 5 phases ----------------
// grid 128 blocks x 256 threads
__global__ __launch_bounds__(256) void dec_scan(
    const int* __restrict__ src, const float* __restrict__ XP,
    const float* __restrict__ ENC,
    const float* __restrict__ Wq, const float* __restrict__ bq,
    const float* __restrict__ dWih0, const float* __restrict__ dWhh0,
    const float* __restrict__ dWih1, const float* __restrict__ dWhh1,
    const float* __restrict__ B1,
    const float* __restrict__ Wout, const float* __restrict__ bout,
    float* __restrict__ D0HT, float* __restrict__ D1HT,
    float* __restrict__ D0CT, float* __restrict__ D1CT,
    float* __restrict__ Q, float* __restrict__ CTX,
    float* __restrict__ out, unsigned* __restrict__ bar)
{
    __shared__ __align__(16) float SM[9248];
    float* As = SM;              // 32*129 = 4128
    float* Ws = SM + 4128;       // up to 512
    float* sg = SM + 4640;       // 16*129 = 2064
    float* qs = SM;              // attention views (phase-exclusive)
    float* ec = SM + 1024;       // 8*1024
    float* ssc = SM + 9216;      // 8

    const int g = blockIdx.x;
    const int tid = threadIdx.x;
    const int b = tid & 127, half = tid >> 7;
    const int lane = tid & 31, w = tid >> 5;
    unsigned nb = 0;
    const size_t NS = (size_t)CH * CB;

    for (int t = 0; t < CT; t++) {
        const int cur = t & 1, nxt = cur ^ 1;

        // ---- Phase A: q = d1h @ Wq^T + bq ----
        {
            float acc[4] = {};
            mg<8, true>(acc, D1HT + (size_t)cur * NS, 128, Wq, CH, 0, g * 8, 0, CH, As, Ws);
            const int rb = g * 8 + half * 4;
#pragma unroll
            for (int i = 0; i < 4; i++)
                Q[(size_t)b * CH2 + rb + i] = acc[i] + bq[rb + i];
        }
        gbar(bar, (++nb) * 128u);

        // ---- Phase B: attention for batch row g ----
        {
#pragma unroll
            for (int u = 0; u < 4; u++)
                qs[tid + 256 * u] = __ldcg(Q + (size_t)g * CH2 + tid + 256 * u);
            __syncthreads();
            float mrun = -INFINITY, zrun = 0.0f;
            float cacc[4] = {0.f, 0.f, 0.f, 0.f};
            const float* Eb = ENC + (size_t)g * CS * CH2;
            for (int s0 = 0; s0 < CS; s0 += 8) {
#pragma unroll
                for (int u = 0; u < 8; u++) {
                    int li = tid + 256 * u;
                    int si = li >> 8, kq = li & 255;
                    ((float4*)(ec + si * 1024))[kq] =
                        __ldg((const float4*)(Eb + (size_t)(s0 + si) * CH2) + kq);
                }
                __syncthreads();
                float p = 0.0f;
#pragma unroll
                for (int i = 0; i < 32; i++)
                    p += ec[w * 1024 + lane + 32 * i] * qs[lane + 32 * i];
                for (int o = 16; o; o >>= 1) p += __shfl_xor_sync(0xffffffffu, p, o);
                if (lane == 0)
                    ssc[w] = (src[(size_t)g * CS + s0 + w] != 0) ? p : -1e9f;
                __syncthreads();
                float mc = ssc[0];
#pragma unroll
                for (int i = 1; i < 8; i++) mc = fmaxf(mc, ssc[i]);
                float mnew = fmaxf(mrun, mc);
                float r = expf(mrun - mnew);
                float p8[8];
                float zs = 0.0f;
#pragma unroll
                for (int i = 0; i < 8; i++) { p8[i] = expf(ssc[i] - mnew); zs += p8[i]; }
                zrun = zrun * r + zs;
#pragma unroll
                for (int u = 0; u < 4; u++) {
                    int k = tid + 256 * u;
                    float cv = cacc[u] * r;
#pragma unroll
                    for (int i = 0; i < 8; i++) cv += p8[i] * ec[i * 1024 + k];
                    cacc[u] = cv;
                }
                mrun = mnew;
                __syncthreads();
            }
            float inv = 1.0f / zrun;
#pragma unroll
            for (int u = 0; u < 4; u++)
                CTX[(size_t)g * CH2 + tid + 256 * u] = cacc[u] * inv;
        }
        gbar(bar, (++nb) * 128u);

        // ---- Phase C: decoder cell0 (units g*4 .. g*4+3) ----
        {
            float acc[8] = {};
            mg<16, false>(acc, CTX, CH2, dWih0, CE + CH2, CE, g * 4, 1, CH2, As, Ws);
            mg<16, true >(acc, D0HT + (size_t)cur * NS, 128, dWhh0, CH, 0, g * 4, 1, CH, As, Ws);
            const float* pre = XP + ((size_t)t * CB + b) * CH4;
#pragma unroll
            for (int i = 0; i < 8; i++) {
                int ri = half * 8 + i;
                int row = (ri >> 2) * CH + g * 4 + (ri & 3);
                sg[ri * 129 + b] = acc[i] + pre[row];
            }
            __syncthreads();
            if (tid < CB) {
#pragma unroll
                for (int u = 0; u < 4; u++) {
                    float gi = sg[(0 + u) * 129 + tid];
                    float gf = sg[(4 + u) * 129 + tid];
                    float gg = sg[(8 + u) * 129 + tid];
                    float go = sg[(12 + u) * 129 + tid];
                    size_t ci = (size_t)(g * 4 + u) * CB + tid;
                    float c = sigf(gf) * D0CT[ci] + sigf(gi) * tanhf(gg);
                    D0CT[ci] = c;
                    D0HT[(size_t)nxt * NS + ci] = sigf(go) * tanhf(c);
                }
            }
            __syncthreads();
        }
        gbar(bar, (++nb) * 128u);

        // ---- Phase D: decoder cell1 ----
        {
            float acc[8] = {};
            mg<16, true>(acc, D0HT + (size_t)nxt * NS, 128, dWih1, CH, 0, g * 4, 1, CH, As, Ws);
            mg<16, true>(acc, D1HT + (size_t)cur * NS, 128, dWhh1, CH, 0, g * 4, 1, CH, As, Ws);
#pragma unroll
            for (int i = 0; i < 8; i++) {
                int ri = half * 8 + i;
                int row = (ri >> 2) * CH + g * 4 + (ri & 3);
                sg[ri * 129 + b] = acc[i] + B1[row];
            }
            __syncthreads();
            if (tid < CB) {
#pragma unroll
                for (int u = 0; u < 4; u++) {
                    float gi = sg[(0 + u) * 129 + tid];
                    float gf = sg[(4 + u) * 129 + tid];
                    float gg = sg[(8 + u) * 129 + tid];
                    float go = sg[(12 + u) * 129 + tid];
                    size_t ci = (size_t)(g * 4 + u) * CB + tid;
                    float c = sigf(gf) * D1CT[ci] + sigf(gi) * tanhf(gg);
                    D1CT[ci] = c;
                    D1HT[(size_t)nxt * NS + ci] = sigf(go) * tanhf(c);
                }
            }
            __syncthreads();
        }
        gbar(bar, (++nb) * 128u);

        // ---- Phase E: logits (vocab cols g*4 .. g*4+3) ----
        {
            float acc[2] = {};
            mg<4, true>(acc, D1HT + (size_t)nxt * NS, 128, Wout, CH, 0, g * 4, 0, CH, As, Ws);
            const int vb = g * 4 + half * 2;
#pragma unroll
            for (int i = 0; i < 2; i++)
                out[(size_t)b * CT * CV + (size_t)t * CV + vb + i] = acc[i] + bout[vb + i];
        }
        // no barrier needed: next phase A's inputs were fenced at barrier after D
    }
}

// ---------------- host orchestration ----------------
extern "C" void kernel_launch(void* const* d_in, const int* in_sizes, int n_in,
                              void* d_out, int out_size)
{
    const int*   src    = (const int*)d_in[0];
    const int*   din    = (const int*)d_in[1];
    const float* emb    = (const float*)d_in[2];
    const float* eWih0  = (const float*)d_in[3];
    const float* eWhh0  = (const float*)d_in[4];
    const float* ebih0  = (const float*)d_in[5];
    const float* ebhh0  = (const float*)d_in[6];
    const float* eWih1  = (const float*)d_in[7];
    const float* eWhh1  = (const float*)d_in[8];
    const float* ebih1  = (const float*)d_in[9];
    const float* ebhh1  = (const float*)d_in[10];
    const float* dWih0  = (const float*)d_in[11];
    const float* dWhh0  = (const float*)d_in[12];
    const float* dbih0  = (const float*)d_in[13];
    const float* dbhh0  = (const float*)d_in[14];
    const float* dWih1  = (const float*)d_in[15];
    const float* dWhh1  = (const float*)d_in[16];
    const float* dbih1  = (const float*)d_in[17];
    const float* dbhh1  = (const float*)d_in[18];
    const float* Wq     = (const float*)d_in[19];
    const float* bq     = (const float*)d_in[20];
    const float* Wout   = (const float*)d_in[21];
    const float* bout   = (const float*)d_in[22];
    float* out = (float*)d_out;

    float *XS, *DE, *XP, *Y0, *ENC, *HB, *SC, *D0H, *D1H, *D0C, *D1C, *CTX, *Q, *B1;
    unsigned *barE, *barD;
    cudaGetSymbolAddress((void**)&XS,   g_XS);
    cudaGetSymbolAddress((void**)&DE,   g_DE);
    cudaGetSymbolAddress((void**)&XP,   g_XP);
    cudaGetSymbolAddress((void**)&Y0,   g_Y0);
    cudaGetSymbolAddress((void**)&ENC,  g_ENC);
    cudaGetSymbolAddress((void**)&HB,   g_HB);
    cudaGetSymbolAddress((void**)&SC,   g_SC);
    cudaGetSymbolAddress((void**)&D0H,  g_d0h);
    cudaGetSymbolAddress((void**)&D1H,  g_d1h);
    cudaGetSymbolAddress((void**)&D0C,  g_d0c);
    cudaGetSymbolAddress((void**)&D1C,  g_d1c);
    cudaGetSymbolAddress((void**)&CTX,  g_ctx);
    cudaGetSymbolAddress((void**)&Q,    g_q);
    cudaGetSymbolAddress((void**)&B1,   g_b1);
    cudaGetSymbolAddress((void**)&barE, g_barE);
    cudaGetSymbolAddress((void**)&barD, g_barD);

    embed_k<<<1024, 256>>>(emb, src, CS, XS, (long)CS * CB * CE);
    embed_k<<<1024, 256>>>(emb, din, CT, DE, (long)CT * CB * CE);

    // encoder L0 x-projections (biases folded)
    for (int d = 0; d < 2; d++)
        sgemm_bias<<<dim3(CH4 / 64, (CS * CB) / 64), 256>>>(
            CS * CB, CH4, CE, XS, CE,
            eWih0 + (size_t)d * CH4 * CE, CE, 0,
            ebih0 + (size_t)d * CH4, ebhh0 + (size_t)d * CH4,
            XP + (size_t)d * CS * CB * CH4, (long long)CH4);

    cudaMemsetAsync(HB, 0, sizeof(float) * 2 * 2 * CB * CH);
    cudaMemsetAsync(SC, 0, sizeof(float) * 2 * CB * CH);
    cudaMemsetAsync(barE, 0, sizeof(unsigned));
    enc_scan<<<dim3(16, 4, 2), 128>>>(0, XP, eWhh0, HB, SC, Y0, D0H, D0C, barE);

    // encoder L1 x-projections
    for (int d = 0; d < 2; d++)
        sgemm_bias<<<dim3(CH4 / 64, (CS * CB) / 64), 256>>>(
            CS * CB, CH4, CH2, Y0, CH2,
            eWih1 + (size_t)d * CH4 * CH2, CH2, 0,
            ebih1 + (size_t)d * CH4, ebhh1 + (size_t)d * CH4,
            XP + (size_t)d * CS * CB * CH4, (long long)CH4);

    cudaMemsetAsync(HB, 0, sizeof(float) * 2 * 2 * CB * CH);
    cudaMemsetAsync(SC, 0, sizeof(float) * 2 * CB * CH);
    cudaMemsetAsync(barE, 0, sizeof(unsigned));
    enc_scan<<<dim3(16, 4, 2), 128>>>(1, XP, eWhh1, HB, SC, ENC, D1H, D1C, barE);

    // decoder embedding-half projection (biases folded), into XP (reused)
    sgemm_bias<<<dim3(CH4 / 64, (CT * CB) / 64), 256>>>(
        CT * CB, CH4, CE, DE, CE,
        dWih0, CE + CH2, 0, dbih0, dbhh0,
        XP, (long long)CH4);

    vsum_k<<<(CH4 + 255) / 256, 256>>>(dbih1, dbhh1, B1, CH4);

    cudaMemsetAsync(barD, 0, sizeof(unsigned));
    dec_scan<<<128, 256>>>(src, XP, ENC, Wq, bq,
                           dWih0, dWhh0, dWih1, dWhh1, B1, Wout, bout,
                           D0H, D1H, D0C, D1C, Q, CTX, out, barD);
}

// round 4
// speedup vs baseline: 1.3583x; 1.3583x over previous
#include <cuda_runtime.h>
#include <math.h>

#define CB 128
#define CS 256
#define CT 256
#define CV 512
#define CE 256
#define CH 512
#define CH2 1024
#define CH4 2048

// ---------------- static device scratch ----------------
static __device__ float g_XS[(size_t)CS * CB * CE];
static __device__ float g_DE[(size_t)CT * CB * CE];
static __device__ float g_XP[(size_t)2 * CS * CB * CH4];
static __device__ float g_Y0[(size_t)CS * CB * CH2];
static __device__ float g_ENC[(size_t)CB * CS * CH2];
static __device__ float g_HB[(size_t)2 * 2 * CB * CH];   // [buf][dir][b][j]
static __device__ float g_SC[(size_t)2 * CB * CH];       // [dir][b][j]
static __device__ float g_d0h[(size_t)2 * CH * CB];      // transposed [buf][j][b]
static __device__ float g_d1h[(size_t)2 * CH * CB];
static __device__ float g_d0c[(size_t)CH * CB];
static __device__ float g_d1c[(size_t)CH * CB];
static __device__ float g_ctx[(size_t)CB * CH2];
static __device__ float g_q[(size_t)CB * CH2];
static __device__ float g_b1[CH4];
static __device__ unsigned g_barE;
static __device__ unsigned g_barD;

// ---------------- grid barrier (all blocks resident) ----------------
__device__ __forceinline__ void gbar(unsigned* ctr, unsigned target)
{
    __syncthreads();
    if (threadIdx.x == 0) {
        __threadfence();
        atomicAdd(ctr, 1u);
        volatile unsigned* v = ctr;
        while (*v < target) __nanosleep(32);
    }
    __syncthreads();
}

__device__ __forceinline__ float sigf(float x) { return 1.0f / (1.0f + expf(-x)); }

// ---------------- embedding ----------------
__global__ void embed_k(const float* __restrict__ emb, const int* __restrict__ toks,
                        int L, float* __restrict__ X, long total)
{
    for (long i = (long)blockIdx.x * blockDim.x + threadIdx.x; i < total;
         i += (long)gridDim.x * blockDim.x) {
        int e = (int)(i % CE);
        long r = i / CE;
        int b = (int)(r % CB);
        int t = (int)(r / CB);
        int tok = toks[(long)b * L + t];
        X[i] = (tok == 0) ? 0.0f : emb[(long)tok * CE + e];
    }
}

// ---------------- precompute GEMM v2: 128x64 tile, double-buffered ----------------
// C[z][M,N] = A[M,K] * W[z][N, woff..woff+K]^T + b0[z] + b1[z]
__global__ __launch_bounds__(256) void sgemm_bias(
    int M, int N, int K,
    const float* __restrict__ A, int lda,
    const float* __restrict__ W, int ldw, int woff, long long wstride,
    const float* __restrict__ b0, const float* __restrict__ b1, int bstride,
    float* __restrict__ C, long long ldc, long long cstride)
{
    __shared__ float As[16][132];
    __shared__ float Ws[16][68];
    const int z = blockIdx.z;
    W += (size_t)z * wstride;
    C += (size_t)z * cstride;
    const float* bb0 = b0 ? (b0 + (size_t)z * bstride) : 0;
    const float* bb1 = b1 ? (b1 + (size_t)z * bstride) : 0;

    const int bm = blockIdx.y * 128, bn = blockIdx.x * 64;
    const int tid = threadIdx.x;
    const int tx = tid & 15, ty = tid >> 4;
    // A loader: thread i<2: idx = tid + 256*i -> row=idx>>2, ks=idx&3
    const int ar0 = tid >> 2, aks = (tid & 3) * 4;
    // W loader: col = tid>>2, ks same
    const int wc = tid >> 2;

    float4 av[2], wv;
    av[0] = *(const float4*)(A + (size_t)(bm + ar0) * lda + aks);
    av[1] = *(const float4*)(A + (size_t)(bm + ar0 + 64) * lda + aks);
    wv = *(const float4*)(W + (size_t)(bn + wc) * ldw + woff + aks);

    float acc[8][4] = {};
    for (int k0 = 0; k0 < K; k0 += 16) {
        {
            const float* a0 = (const float*)&av[0];
            const float* a1 = (const float*)&av[1];
            const float* w0 = (const float*)&wv;
#pragma unroll
            for (int j = 0; j < 4; j++) {
                As[aks + j][ar0] = a0[j];
                As[aks + j][ar0 + 64] = a1[j];
                Ws[aks + j][wc] = w0[j];
            }
        }
        __syncthreads();
        if (k0 + 16 < K) {
            av[0] = *(const float4*)(A + (size_t)(bm + ar0) * lda + k0 + 16 + aks);
            av[1] = *(const float4*)(A + (size_t)(bm + ar0 + 64) * lda + k0 + 16 + aks);
            wv = *(const float4*)(W + (size_t)(bn + wc) * ldw + woff + k0 + 16 + aks);
        }
#pragma unroll
        for (int kk = 0; kk < 16; kk++) {
            float4 x0 = *(const float4*)&As[kk][ty * 8];
            float4 x1 = *(const float4*)&As[kk][ty * 8 + 4];
            float4 y0 = *(const float4*)&Ws[kk][tx * 4];
            float xr[8] = {x0.x, x0.y, x0.z, x0.w, x1.x, x1.y, x1.z, x1.w};
            float yr[4] = {y0.x, y0.y, y0.z, y0.w};
#pragma unroll
            for (int i = 0; i < 8; i++)
#pragma unroll
                for (int j = 0; j < 4; j++)
                    acc[i][j] += xr[i] * yr[j];
        }
        __syncthreads();
    }
#pragma unroll
    for (int i = 0; i < 8; i++) {
        float4 o;
        float* op = (float*)&o;
#pragma unroll
        for (int j = 0; j < 4; j++) {
            int n = bn + tx * 4 + j;
            float bv = (bb0 ? bb0[n] : 0.0f) + (bb1 ? bb1[n] : 0.0f);
            op[j] = acc[i][j] + bv;
        }
        *(float4*)(C + (long long)(bm + ty * 8 + i) * ldc + bn + tx * 4) = o;
    }
}

__global__ void vsum_k(const float* __restrict__ a, const float* __restrict__ b,
                       float* __restrict__ o, int n)
{
    int i = blockIdx.x * blockDim.x + threadIdx.x;
    if (i < n) o[i] = a[i] + b[i];
}

// ---------------- persistent encoder scan: 256 threads, prefetch ----------------
// grid (16,4,2) = 128 blocks
__global__ __launch_bounds__(256) void enc_scan(
    int layer, const float* __restrict__ XP, const float* __restrict__ Whh,
    float* __restrict__ HB, float* __restrict__ SC, float* __restrict__ Yout,
    float* __restrict__ DHT, float* __restrict__ DCT, unsigned* __restrict__ bar)
{
    __shared__ float hs[32][33];
    __shared__ float ws[4][32][33];
    const int d = blockIdx.z;
    const int j0 = blockIdx.x * 32, b0 = blockIdx.y * 32;
    const int tid = threadIdx.x;
    const int jj = tid & 15, bb = tid >> 4;
    const float* W_d = Whh + (size_t)d * CH4 * CH;
    const int hk = tid & 31, hb = tid >> 5;   // h loader: +8u rows
    const int wk = tid & 31, wr0 = tid >> 5;  // w loader: row = wr0+8u

    for (int t = 0; t < CS; t++) {
        const int td = d ? (CS - 1 - t) : t;
        const float* hin = HB + (size_t)(((t & 1) * 2 + d) * CB) * CH;
        float* hout = HB + (size_t)((((t + 1) & 1) * 2 + d) * CB) * CH;

        float acc[4][2][2] = {};
        float hr[4], wreg[16];
#pragma unroll
        for (int u = 0; u < 4; u++)
            hr[u] = __ldcg(hin + (size_t)(b0 + hb + 8 * u) * CH + hk);
#pragma unroll
        for (int u = 0; u < 16; u++) {
            int row = wr0 + 8 * u;
            int g = row >> 5, j = row & 31;
            wreg[u] = W_d[(size_t)(g * CH + j0 + j) * CH + wk];
        }
        for (int k0 = 0; k0 < CH; k0 += 32) {
#pragma unroll
            for (int u = 0; u < 4; u++) hs[hk][hb + 8 * u] = hr[u];
#pragma unroll
            for (int u = 0; u < 16; u++) {
                int row = wr0 + 8 * u;
                int g = row >> 5, j = row & 31;
                ws[g][wk][j] = wreg[u];
            }
            __syncthreads();
            if (k0 + 32 < CH) {
#pragma unroll
                for (int u = 0; u < 4; u++)
                    hr[u] = __ldcg(hin + (size_t)(b0 + hb + 8 * u) * CH + k0 + 32 + hk);
#pragma unroll
                for (int u = 0; u < 16; u++) {
                    int row = wr0 + 8 * u;
                    int g = row >> 5, j = row & 31;
                    wreg[u] = W_d[(size_t)(g * CH + j0 + j) * CH + k0 + 32 + wk];
                }
            }
#pragma unroll
            for (int kk = 0; kk < 32; kk++) {
                float h0 = hs[kk][bb], h1 = hs[kk][bb + 16];
#pragma unroll
                for (int g = 0; g < 4; g++) {
                    float w0 = ws[g][kk][jj], w1 = ws[g][kk][jj + 16];
                    acc[g][0][0] += h0 * w0;
                    acc[g][1][0] += h1 * w0;
                    acc[g][0][1] += h0 * w1;
                    acc[g][1][1] += h1 * w1;
                }
            }
            __syncthreads();
        }
        const float* pre = XP + ((size_t)d * CS + td) * CB * CH4;
#pragma unroll
        for (int bi = 0; bi < 2; bi++) {
            int b = b0 + bb + 16 * bi;
            const float* prow = pre + (size_t)b * CH4;
#pragma unroll
            for (int m = 0; m < 2; m++) {
                int j = j0 + jj + 16 * m;
                float gi = acc[0][bi][m] + prow[j];
                float gf = acc[1][bi][m] + prow[CH + j];
                float gg = acc[2][bi][m] + prow[2 * CH + j];
                float go = acc[3][bi][m] + prow[3 * CH + j];
                size_t ci = (size_t)(d * CB + b) * CH + j;
                float c = sigf(gf) * SC[ci] + sigf(gi) * tanhf(gg);
                SC[ci] = c;
                float h = sigf(go) * tanhf(c);
                hout[(size_t)b * CH + j] = h;
                size_t yi = (layer == 0)
                    ? ((size_t)td * CB + b) * CH2 + (size_t)d * CH + j
                    : ((size_t)b * CS + td) * CH2 + (size_t)d * CH + j;
                Yout[yi] = h;
            }
        }
        gbar(bar, (unsigned)(t + 1) * 128u);
    }
    // epilogue: summed bidirectional final states, transposed [j][b]
    if (d == 0) {
#pragma unroll
        for (int u = 0; u < 4; u++) {
            int li = tid + 256 * u;
            int j = li >> 5, b = li & 31;
            int gj = j0 + j, gb = b0 + b;
            float hf = __ldcg(HB + (size_t)(0 * CB + gb) * CH + gj);
            float hbv = __ldcg(HB + (size_t)(1 * CB + gb) * CH + gj);
            DHT[(size_t)gj * CB + gb] = hf + hbv;
            float cf = __ldcg(SC + (size_t)(0 * CB + gb) * CH + gj);
            float cbv = __ldcg(SC + (size_t)(CB + gb) * CH + gj);
            DCT[(size_t)gj * CB + gb] = cf + cbv;
        }
    }
}

// ---------------- decoder micro-GEMM: 512 threads, prefetch ----------------
// thread (b = tid&127, q = tid>>7) accumulates NT=NR/4 rows: ri = q*NT + i
// rmode 0: W row = rbase+ri ; rmode 1: row = (ri>>2)*CH + rbase + (ri&3)
template<int NR, bool AT>
__device__ __forceinline__ void mg(
    float* __restrict__ acc, const float* __restrict__ A, int lda,
    const float* __restrict__ W, int ldw, int woff,
    int rbase, int rmode, int K,
    float* __restrict__ As, float* __restrict__ Ws)
{
    const int tid = threadIdx.x;
    const int b = tid & 127, q = tid >> 7;
    constexpr int NT = NR / 4;
    constexpr int NRP = NR + 1;
    const int wk = tid & 31, wri = tid >> 5;
    const bool wact = (tid < 32 * NR);
    int wrow = 0;
    if (wact)
        wrow = (rmode == 0) ? (rbase + wri)
                            : ((wri >> 2) * CH + rbase + (wri & 3));

    float ar[8], wv = 0.0f;
#pragma unroll
    for (int u = 0; u < 8; u++) {
        if (AT) ar[u] = __ldcg(A + (size_t)(q + 4 * u) * 128 + b);
        else    ar[u] = __ldcg(A + (size_t)((tid >> 5) + 16 * u) * lda + (tid & 31));
    }
    if (wact) wv = W[(size_t)wrow * ldw + woff + wk];

    for (int k0 = 0; k0 < K; k0 += 32) {
#pragma unroll
        for (int u = 0; u < 8; u++) {
            if (AT) As[(q + 4 * u) * 129 + b] = ar[u];
            else    As[(tid & 31) * 129 + (tid >> 5) + 16 * u] = ar[u];
        }
        if (wact) Ws[wk * NRP + wri] = wv;
        __syncthreads();
        if (k0 + 32 < K) {
#pragma unroll
            for (int u = 0; u < 8; u++) {
                if (AT) ar[u] = __ldcg(A + (size_t)(k0 + 32 + q + 4 * u) * 128 + b);
                else    ar[u] = __ldcg(A + (size_t)((tid >> 5) + 16 * u) * lda + k0 + 32 + (tid & 31));
            }
            if (wact) wv = W[(size_t)wrow * ldw + woff + k0 + 32 + wk];
        }
#pragma unroll
        for (int kk = 0; kk < 32; kk++) {
            float a = As[kk * 129 + b];
#pragma unroll
            for (int i = 0; i < NT; i++)
                acc[i] += a * Ws[kk * NRP + q * NT + i];
        }
        __syncthreads();
    }
}

// ---------------- persistent decoder: 128 blocks x 512 threads ----------------
__global__ __launch_bounds__(512) void dec_scan(
    const int* __restrict__ src, const float* __restrict__ XP,
    const float* __restrict__ ENC,
    const float* __restrict__ Wq, const float* __restrict__ bq,
    const float* __restrict__ dWih0, const float* __restrict__ dWhh0,
    const float* __restrict__ dWih1, const float* __restrict__ dWhh1,
    const float* __restrict__ B1,
    const float* __restrict__ Wout, const float* __restrict__ bout,
    float* __restrict__ D0HT, float* __restrict__ D1HT,
    float* __restrict__ D0CT, float* __restrict__ D1CT,
    float* __restrict__ Q, float* __restrict__ CTX,
    float* __restrict__ out, unsigned* __restrict__ bar)
{
    __shared__ __align__(16) float SM[9248];
    float* As = SM;              // 32*129 = 4128
    float* Ws = SM + 4128;       // 32*17 = 544
    float* sg = SM + 4672;       // 16*129 = 2064
    float* qs = SM;              // attention views (phase exclusive)
    float* ec = SM + 1024;       // 8*1024
    float* ssc = SM + 9216;      // 8

    const int g = blockIdx.x;
    const int tid = threadIdx.x;
    const int b = tid & 127, q = tid >> 7;
    const int lane = tid & 31, w = tid >> 5;
    unsigned nb = 0;
    const size_t NS = (size_t)CH * CB;

    for (int t = 0; t < CT; t++) {
        const int cur = t & 1, nxt = cur ^ 1;

        // ---- Phase A: q = d1h @ Wq^T + bq (rows g*8..g*8+7, all batches) ----
        {
            float acc[2] = {};
            mg<8, true>(acc, D1HT + (size_t)cur * NS, 128, Wq, CH, 0, g * 8, 0, CH, As, Ws);
            const int rb = g * 8 + q * 2;
#pragma unroll
            for (int i = 0; i < 2; i++)
                Q[(size_t)b * CH2 + rb + i] = acc[i] + bq[rb + i];
        }
        gbar(bar, (++nb) * 128u);

        // ---- Phase B: attention for batch row g ----
        {
            qs[tid] = __ldcg(Q + (size_t)g * CH2 + tid);
            qs[tid + 512] = __ldcg(Q + (size_t)g * CH2 + tid + 512);
            __syncthreads();
            float mrun = -INFINITY, zrun = 0.0f;
            float cacc[2] = {0.f, 0.f};
            const float* Eb = ENC + (size_t)g * CS * CH2;
            for (int s0 = 0; s0 < CS; s0 += 8) {
#pragma unroll
                for (int u = 0; u < 4; u++) {
                    int li = tid + 512 * u;
                    int si = li >> 8, kq = li & 255;
                    ((float4*)(ec + si * 1024))[kq] =
                        __ldg((const float4*)(Eb + (size_t)(s0 + si) * CH2) + kq);
                }
                __syncthreads();
                if (w < 8) {
                    float p = 0.0f;
#pragma unroll
                    for (int i = 0; i < 32; i++)
                        p += ec[w * 1024 + lane + 32 * i] * qs[lane + 32 * i];
                    for (int o = 16; o; o >>= 1) p += __shfl_xor_sync(0xffffffffu, p, o);
                    if (lane == 0)
                        ssc[w] = (src[(size_t)g * CS + s0 + w] != 0) ? p : -1e9f;
                }
                __syncthreads();
                float mc = ssc[0];
#pragma unroll
                for (int i = 1; i < 8; i++) mc = fmaxf(mc, ssc[i]);
                float mnew = fmaxf(mrun, mc);
                float r = expf(mrun - mnew);
                float p8[8];
                float zs = 0.0f;
#pragma unroll
                for (int i = 0; i < 8; i++) { p8[i] = expf(ssc[i] - mnew); zs += p8[i]; }
                zrun = zrun * r + zs;
#pragma unroll
                for (int u = 0; u < 2; u++) {
                    int k = tid + 512 * u;
                    float cv = cacc[u] * r;
#pragma unroll
                    for (int i = 0; i < 8; i++) cv += p8[i] * ec[i * 1024 + k];
                    cacc[u] = cv;
                }
                mrun = mnew;
                __syncthreads();
            }
            float inv = 1.0f / zrun;
#pragma unroll
            for (int u = 0; u < 2; u++)
                CTX[(size_t)g * CH2 + tid + 512 * u] = cacc[u] * inv;
        }
        gbar(bar, (++nb) * 128u);

        // ---- Phase C: decoder cell0 (units g*4..g*4+3) ----
        {
            float acc[4] = {};
            mg<16, false>(acc, CTX, CH2, dWih0, CE + CH2, CE, g * 4, 1, CH2, As, Ws);
            mg<16, true >(acc, D0HT + (size_t)cur * NS, 128, dWhh0, CH, 0, g * 4, 1, CH, As, Ws);
            const float* pre = XP + ((size_t)t * CB + b) * CH4;
#pragma unroll
            for (int i = 0; i < 4; i++) {
                int ri = q * 4 + i;
                int row = q * CH + g * 4 + i;
                sg[ri * 129 + b] = acc[i] + pre[row];
            }
            __syncthreads();
            if (tid < CB) {
#pragma unroll
                for (int u = 0; u < 4; u++) {
                    float gi = sg[(0 + u) * 129 + tid];
                    float gf = sg[(4 + u) * 129 + tid];
                    float gg = sg[(8 + u) * 129 + tid];
                    float go = sg[(12 + u) * 129 + tid];
                    size_t ci = (size_t)(g * 4 + u) * CB + tid;
                    float c = sigf(gf) * D0CT[ci] + sigf(gi) * tanhf(gg);
                    D0CT[ci] = c;
                    D0HT[(size_t)nxt * NS + ci] = sigf(go) * tanhf(c);
                }
            }
            __syncthreads();
        }
        gbar(bar, (++nb) * 128u);

        // ---- Phase D: decoder cell1 ----
        {
            float acc[4] = {};
            mg<16, true>(acc, D0HT + (size_t)nxt * NS, 128, dWih1, CH, 0, g * 4, 1, CH, As, Ws);
            mg<16, true>(acc, D1HT + (size_t)cur * NS, 128, dWhh1, CH, 0, g * 4, 1, CH, As, Ws);
#pragma unroll
            for (int i = 0; i < 4; i++) {
                int ri = q * 4 + i;
                int row = q * CH + g * 4 + i;
                sg[ri * 129 + b] = acc[i] + B1[row];
            }
            __syncthreads();
            if (tid < CB) {
#pragma unroll
                for (int u = 0; u < 4; u++) {
                    float gi = sg[(0 + u) * 129 + tid];
                    float gf = sg[(4 + u) * 129 + tid];
                    float gg = sg[(8 + u) * 129 + tid];
                    float go = sg[(12 + u) * 129 + tid];
                    size_t ci = (size_t)(g * 4 + u) * CB + tid;
                    float c = sigf(gf) * D1CT[ci] + sigf(gi) * tanhf(gg);
                    D1CT[ci] = c;
                    D1HT[(size_t)nxt * NS + ci] = sigf(go) * tanhf(c);
                }
            }
            __syncthreads();
        }
        gbar(bar, (++nb) * 128u);

        // ---- Phase E: logits (vocab cols g*4..g*4+3) ----
        {
            float acc1[1] = {};
            mg<4, true>(acc1, D1HT + (size_t)nxt * NS, 128, Wout, CH, 0, g * 4, 0, CH, As, Ws);
            const int vb = g * 4 + q;
            out[(size_t)b * CT * CV + (size_t)t * CV + vb] = acc1[0] + bout[vb];
        }
        // no barrier: E and next-A both only read D1HT[nxt]; Q rewrite is safe
    }
}

// ---------------- host orchestration ----------------
extern "C" void kernel_launch(void* const* d_in, const int* in_sizes, int n_in,
                              void* d_out, int out_size)
{
    const int*   src    = (const int*)d_in[0];
    const int*   din    = (const int*)d_in[1];
    const float* emb    = (const float*)d_in[2];
    const float* eWih0  = (const float*)d_in[3];
    const float* eWhh0  = (const float*)d_in[4];
    const float* ebih0  = (const float*)d_in[5];
    const float* ebhh0  = (const float*)d_in[6];
    const float* eWih1  = (const float*)d_in[7];
    const float* eWhh1  = (const float*)d_in[8];
    const float* ebih1  = (const float*)d_in[9];
    const float* ebhh1  = (const float*)d_in[10];
    const float* dWih0  = (const float*)d_in[11];
    const float* dWhh0  = (const float*)d_in[12];
    const float* dbih0  = (const float*)d_in[13];
    const float* dbhh0  = (const float*)d_in[14];
    const float* dWih1  = (const float*)d_in[15];
    const float* dWhh1  = (const float*)d_in[16];
    const float* dbih1  = (const float*)d_in[17];
    const float* dbhh1  = (const float*)d_in[18];
    const float* Wq     = (const float*)d_in[19];
    const float* bq     = (const float*)d_in[20];
    const float* Wout   = (const float*)d_in[21];
    const float* bout   = (const float*)d_in[22];
    float* out = (float*)d_out;

    float *XS, *DE, *XP, *Y0, *ENC, *HB, *SC, *D0H, *D1H, *D0C, *D1C, *CTX, *Q, *B1;
    unsigned *barE, *barD;
    cudaGetSymbolAddress((void**)&XS,   g_XS);
    cudaGetSymbolAddress((void**)&DE,   g_DE);
    cudaGetSymbolAddress((void**)&XP,   g_XP);
    cudaGetSymbolAddress((void**)&Y0,   g_Y0);
    cudaGetSymbolAddress((void**)&ENC,  g_ENC);
    cudaGetSymbolAddress((void**)&HB,   g_HB);
    cudaGetSymbolAddress((void**)&SC,   g_SC);
    cudaGetSymbolAddress((void**)&D0H,  g_d0h);
    cudaGetSymbolAddress((void**)&D1H,  g_d1h);
    cudaGetSymbolAddress((void**)&D0C,  g_d0c);
    cudaGetSymbolAddress((void**)&D1C,  g_d1c);
    cudaGetSymbolAddress((void**)&CTX,  g_ctx);
    cudaGetSymbolAddress((void**)&Q,    g_q);
    cudaGetSymbolAddress((void**)&B1,   g_b1);
    cudaGetSymbolAddress((void**)&barE, g_barE);
    cudaGetSymbolAddress((void**)&barD, g_barD);

    embed_k<<<1024, 256>>>(emb, src, CS, XS, (long)CS * CB * CE);
    embed_k<<<1024, 256>>>(emb, din, CT, DE, (long)CT * CB * CE);

    // encoder L0 x-projections: both dirs in one launch (z)
    sgemm_bias<<<dim3(CH4 / 64, (CS * CB) / 128, 2), 256>>>(
        CS * CB, CH4, CE, XS, CE,
        eWih0, CE, 0, (long long)CH4 * CE,
        ebih0, ebhh0, CH4,
        XP, (long long)CH4, (long long)CS * CB * CH4);

    cudaMemsetAsync(HB, 0, sizeof(float) * 2 * 2 * CB * CH);
    cudaMemsetAsync(SC, 0, sizeof(float) * 2 * CB * CH);
    cudaMemsetAsync(barE, 0, sizeof(unsigned));
    enc_scan<<<dim3(16, 4, 2), 256>>>(0, XP, eWhh0, HB, SC, Y0, D0H, D0C, barE);

    // encoder L1 x-projections
    sgemm_bias<<<dim3(CH4 / 64, (CS * CB) / 128, 2), 256>>>(
        CS * CB, CH4, CH2, Y0, CH2,
        eWih1, CH2, 0, (long long)CH4 * CH2,
        ebih1, ebhh1, CH4,
        XP, (long long)CH4, (long long)CS * CB * CH4);

    cudaMemsetAsync(HB, 0, sizeof(float) * 2 * 2 * CB * CH);
    cudaMemsetAsync(SC, 0, sizeof(float) * 2 * CB * CH);
    cudaMemsetAsync(barE, 0, sizeof(unsigned));
    enc_scan<<<dim3(16, 4, 2), 256>>>(1, XP, eWhh1, HB, SC, ENC, D1H, D1C, barE);

    // decoder embedding-half projection (biases folded), into XP (reused)
    sgemm_bias<<<dim3(CH4 / 64, (CT * CB) / 128, 1), 256>>>(
        CT * CB, CH4, CE, DE, CE,
        dWih0, CE + CH2, 0, 0,
        dbih0, dbhh0, 0,
        XP, (long long)CH4, 0);

    vsum_k<<<(CH4 + 255) / 256, 256>>>(dbih1, dbhh1, B1, CH4);

    cudaMemsetAsync(barD, 0, sizeof(unsigned));
    dec_scan<<<128, 512>>>(src, XP, ENC, Wq, bq,
                           dWih0, dWhh0, dWih1, dWhh1, B1, Wout, bout,
                           D0H, D1H, D0C, D1C, Q, CTX, out, barD);
}

// round 5
// speedup vs baseline: 1.6775x; 1.2350x over previous
#include <cuda_runtime.h>
#include <math.h>

#define CB 128
#define CS 256
#define CT 256
#define CV 512
#define CE 256
#define CH 512
#define CH2 1024
#define CH4 2048

// ---------------- static device scratch ----------------
static __device__ float g_XS[(size_t)CS * CB * CE];
static __device__ float g_DE[(size_t)CT * CB * CE];
static __device__ float g_XP[(size_t)2 * CS * CB * CH4];
static __device__ float g_Y0[(size_t)CS * CB * CH2];
static __device__ float g_ENC[(size_t)CB * CS * CH2];
static __device__ float g_HB[(size_t)2 * 2 * CB * CH];   // [buf][dir][b][j]
static __device__ float g_SC[(size_t)2 * CB * CH];       // [dir][b][j]
static __device__ float g_d0h[(size_t)2 * CH * CB];      // transposed [buf][j][b]
static __device__ float g_d1h[(size_t)2 * CH * CB];
static __device__ float g_d0c[(size_t)CH * CB];
static __device__ float g_d1c[(size_t)CH * CB];
static __device__ float g_ctxT[(size_t)CH2 * CB];        // transposed [k][b]
static __device__ float g_q[(size_t)CB * CH2];
static __device__ float g_b1[CH4];
static __device__ unsigned g_barE;
static __device__ unsigned g_barD;

// ---------------- grid barrier (all blocks resident) ----------------
__device__ __forceinline__ void gbar(unsigned* ctr, unsigned target)
{
    __syncthreads();
    if (threadIdx.x == 0) {
        __threadfence();
        atomicAdd(ctr, 1u);
        volatile unsigned* v = ctr;
        while (*v < target) __nanosleep(32);
    }
    __syncthreads();
}

__device__ __forceinline__ float sigf(float x) { return 1.0f / (1.0f + expf(-x)); }

// ---------------- embedding ----------------
__global__ void embed_k(const float* __restrict__ emb, const int* __restrict__ toks,
                        int L, float* __restrict__ X, long total)
{
    for (long i = (long)blockIdx.x * blockDim.x + threadIdx.x; i < total;
         i += (long)gridDim.x * blockDim.x) {
        int e = (int)(i % CE);
        long r = i / CE;
        int b = (int)(r % CB);
        int t = (int)(r / CB);
        int tok = toks[(long)b * L + t];
        X[i] = (tok == 0) ? 0.0f : emb[(long)tok * CE + e];
    }
}

// ---------------- precompute GEMM: 128x64 tile, double-buffered ----------------
__global__ __launch_bounds__(256) void sgemm_bias(
    int M, int N, int K,
    const float* __restrict__ A, int lda,
    const float* __restrict__ W, int ldw, int woff, long long wstride,
    const float* __restrict__ b0, const float* __restrict__ b1, int bstride,
    float* __restrict__ C, long long ldc, long long cstride)
{
    __shared__ float As[16][132];
    __shared__ float Ws[16][68];
    const int z = blockIdx.z;
    W += (size_t)z * wstride;
    C += (size_t)z * cstride;
    const float* bb0 = b0 ? (b0 + (size_t)z * bstride) : 0;
    const float* bb1 = b1 ? (b1 + (size_t)z * bstride) : 0;

    const int bm = blockIdx.y * 128, bn = blockIdx.x * 64;
    const int tid = threadIdx.x;
    const int tx = tid & 15, ty = tid >> 4;
    const int ar0 = tid >> 2, aks = (tid & 3) * 4;
    const int wc = tid >> 2;

    float4 av[2], wv;
    av[0] = *(const float4*)(A + (size_t)(bm + ar0) * lda + aks);
    av[1] = *(const float4*)(A + (size_t)(bm + ar0 + 64) * lda + aks);
    wv = *(const float4*)(W + (size_t)(bn + wc) * ldw + woff + aks);

    float acc[8][4] = {};
    for (int k0 = 0; k0 < K; k0 += 16) {
        {
            const float* a0 = (const float*)&av[0];
            const float* a1 = (const float*)&av[1];
            const float* w0 = (const float*)&wv;
#pragma unroll
            for (int j = 0; j < 4; j++) {
                As[aks + j][ar0] = a0[j];
                As[aks + j][ar0 + 64] = a1[j];
                Ws[aks + j][wc] = w0[j];
            }
        }
        __syncthreads();
        if (k0 + 16 < K) {
            av[0] = *(const float4*)(A + (size_t)(bm + ar0) * lda + k0 + 16 + aks);
            av[1] = *(const float4*)(A + (size_t)(bm + ar0 + 64) * lda + k0 + 16 + aks);
            wv = *(const float4*)(W + (size_t)(bn + wc) * ldw + woff + k0 + 16 + aks);
        }
#pragma unroll
        for (int kk = 0; kk < 16; kk++) {
            float4 x0 = *(const float4*)&As[kk][ty * 8];
            float4 x1 = *(const float4*)&As[kk][ty * 8 + 4];
            float4 y0 = *(const float4*)&Ws[kk][tx * 4];
            float xr[8] = {x0.x, x0.y, x0.z, x0.w, x1.x, x1.y, x1.z, x1.w};
            float yr[4] = {y0.x, y0.y, y0.z, y0.w};
#pragma unroll
            for (int i = 0; i < 8; i++)
#pragma unroll
                for (int j = 0; j < 4; j++)
                    acc[i][j] += xr[i] * yr[j];
        }
        __syncthreads();
    }
#pragma unroll
    for (int i = 0; i < 8; i++) {
        float4 o;
        float* op = (float*)&o;
#pragma unroll
        for (int j = 0; j < 4; j++) {
            int n = bn + tx * 4 + j;
            float bv = (bb0 ? bb0[n] : 0.0f) + (bb1 ? bb1[n] : 0.0f);
            op[j] = acc[i][j] + bv;
        }
        *(float4*)(C + (long long)(bm + ty * 8 + i) * ldc + bn + tx * 4) = o;
    }
}

__global__ void vsum_k(const float* __restrict__ a, const float* __restrict__ b,
                       float* __restrict__ o, int n)
{
    int i = blockIdx.x * blockDim.x + threadIdx.x;
    if (i < n) o[i] = a[i] + b[i];
}

// ---------------- persistent encoder scan (unchanged from R4) ----------------
__global__ __launch_bounds__(256) void enc_scan(
    int layer, const float* __restrict__ XP, const float* __restrict__ Whh,
    float* __restrict__ HB, float* __restrict__ SC, float* __restrict__ Yout,
    float* __restrict__ DHT, float* __restrict__ DCT, unsigned* __restrict__ bar)
{
    __shared__ float hs[32][33];
    __shared__ float ws[4][32][33];
    const int d = blockIdx.z;
    const int j0 = blockIdx.x * 32, b0 = blockIdx.y * 32;
    const int tid = threadIdx.x;
    const int jj = tid & 15, bb = tid >> 4;
    const float* W_d = Whh + (size_t)d * CH4 * CH;
    const int hk = tid & 31, hb = tid >> 5;
    const int wk = tid & 31, wr0 = tid >> 5;

    for (int t = 0; t < CS; t++) {
        const int td = d ? (CS - 1 - t) : t;
        const float* hin = HB + (size_t)(((t & 1) * 2 + d) * CB) * CH;
        float* hout = HB + (size_t)((((t + 1) & 1) * 2 + d) * CB) * CH;

        float acc[4][2][2] = {};
        float hr[4], wreg[16];
#pragma unroll
        for (int u = 0; u < 4; u++)
            hr[u] = __ldcg(hin + (size_t)(b0 + hb + 8 * u) * CH + hk);
#pragma unroll
        for (int u = 0; u < 16; u++) {
            int row = wr0 + 8 * u;
            int g = row >> 5, j = row & 31;
            wreg[u] = W_d[(size_t)(g * CH + j0 + j) * CH + wk];
        }
        for (int k0 = 0; k0 < CH; k0 += 32) {
#pragma unroll
            for (int u = 0; u < 4; u++) hs[hk][hb + 8 * u] = hr[u];
#pragma unroll
            for (int u = 0; u < 16; u++) {
                int row = wr0 + 8 * u;
                int g = row >> 5, j = row & 31;
                ws[g][wk][j] = wreg[u];
            }
            __syncthreads();
            if (k0 + 32 < CH) {
#pragma unroll
                for (int u = 0; u < 4; u++)
                    hr[u] = __ldcg(hin + (size_t)(b0 + hb + 8 * u) * CH + k0 + 32 + hk);
#pragma unroll
                for (int u = 0; u < 16; u++) {
                    int row = wr0 + 8 * u;
                    int g = row >> 5, j = row & 31;
                    wreg[u] = W_d[(size_t)(g * CH + j0 + j) * CH + k0 + 32 + wk];
                }
            }
#pragma unroll
            for (int kk = 0; kk < 32; kk++) {
                float h0 = hs[kk][bb], h1 = hs[kk][bb + 16];
#pragma unroll
                for (int g = 0; g < 4; g++) {
                    float w0 = ws[g][kk][jj], w1 = ws[g][kk][jj + 16];
                    acc[g][0][0] += h0 * w0;
                    acc[g][1][0] += h1 * w0;
                    acc[g][0][1] += h0 * w1;
                    acc[g][1][1] += h1 * w1;
                }
            }
            __syncthreads();
        }
        const float* pre = XP + ((size_t)d * CS + td) * CB * CH4;
#pragma unroll
        for (int bi = 0; bi < 2; bi++) {
            int b = b0 + bb + 16 * bi;
            const float* prow = pre + (size_t)b * CH4;
#pragma unroll
            for (int m = 0; m < 2; m++) {
                int j = j0 + jj + 16 * m;
                float gi = acc[0][bi][m] + prow[j];
                float gf = acc[1][bi][m] + prow[CH + j];
                float gg = acc[2][bi][m] + prow[2 * CH + j];
                float go = acc[3][bi][m] + prow[3 * CH + j];
                size_t ci = (size_t)(d * CB + b) * CH + j;
                float c = sigf(gf) * SC[ci] + sigf(gi) * tanhf(gg);
                SC[ci] = c;
                float h = sigf(go) * tanhf(c);
                hout[(size_t)b * CH + j] = h;
                size_t yi = (layer == 0)
                    ? ((size_t)td * CB + b) * CH2 + (size_t)d * CH + j
                    : ((size_t)b * CS + td) * CH2 + (size_t)d * CH + j;
                Yout[yi] = h;
            }
        }
        gbar(bar, (unsigned)(t + 1) * 128u);
    }
    if (d == 0) {
#pragma unroll
        for (int u = 0; u < 4; u++) {
            int li = tid + 256 * u;
            int j = li >> 5, b = li & 31;
            int gj = j0 + j, gb = b0 + b;
            float hf = __ldcg(HB + (size_t)(0 * CB + gb) * CH + gj);
            float hbv = __ldcg(HB + (size_t)(1 * CB + gb) * CH + gj);
            DHT[(size_t)gj * CB + gb] = hf + hbv;
            float cf = __ldcg(SC + (size_t)(0 * CB + gb) * CH + gj);
            float cbv = __ldcg(SC + (size_t)(CB + gb) * CH + gj);
            DCT[(size_t)gj * CB + gb] = cf + cbv;
        }
    }
}

// ---------------- decoder micro-GEMM v2: split-K, register tiles ----------------
// 512 threads = 4 kgroups x 128. Thread tile TR x TB. nTR=16, nTB=8.
// AT: [K][128] activations (transposed). W row-major.
// ROWMODE 0: row = rbase + r' ; ROWMODE 1: row = (r'>>4)*CH + rbase + (r'&15)
template<int RPB, int BPB, int ROWMODE>
__device__ __forceinline__ void mgx(
    float* acc,
    const float* __restrict__ AT, int b0,
    const float* __restrict__ W, int ldw, int woff, int rbase, int K,
    float* __restrict__ As, float* __restrict__ Ws)
{
    constexpr int TR = RPB / 16, TB = BPB / 8;
    constexpr int ASTR = BPB + 4;
    constexpr int NA = (32 * BPB) / 512;
    constexpr int NW = (32 * RPB) / 512;
    const int tid = threadIdx.x;
    const int kg = tid >> 7, t = tid & 127;
    const int trow = t >> 3, tcol = t & 7;

    int wrow[NW];
#pragma unroll
    for (int u = 0; u < NW; u++) {
        int rp = (tid + 512 * u) >> 5;
        wrow[u] = (ROWMODE == 0) ? (rbase + rp)
                                 : ((rp >> 4) * CH + rbase + (rp & 15));
    }
    float areg[NA], wreg[NW];
#pragma unroll
    for (int u = 0; u < NA; u++) {
        int idx = tid + 512 * u;
        int k = idx / BPB, bp = idx % BPB;
        areg[u] = __ldcg(AT + (size_t)k * 128 + b0 + bp);
    }
#pragma unroll
    for (int u = 0; u < NW; u++) {
        int k = (tid + 512 * u) & 31;
        wreg[u] = __ldg(W + (size_t)wrow[u] * ldw + woff + k);
    }
    for (int k0 = 0; k0 < K; k0 += 32) {
#pragma unroll
        for (int u = 0; u < NA; u++) {
            int idx = tid + 512 * u;
            int k = idx / BPB, bp = idx % BPB;
            As[k * ASTR + bp] = areg[u];
        }
#pragma unroll
        for (int u = 0; u < NW; u++) {
            int idx = tid + 512 * u;
            Ws[(idx >> 5) * 33 + (idx & 31)] = wreg[u];
        }
        __syncthreads();
        if (k0 + 32 < K) {
#pragma unroll
            for (int u = 0; u < NA; u++) {
                int idx = tid + 512 * u;
                int k = idx / BPB, bp = idx % BPB;
                areg[u] = __ldcg(AT + (size_t)(k0 + 32 + k) * 128 + b0 + bp);
            }
#pragma unroll
            for (int u = 0; u < NW; u++) {
                int k = (tid + 512 * u) & 31;
                wreg[u] = __ldg(W + (size_t)wrow[u] * ldw + woff + k0 + 32 + k);
            }
        }
#pragma unroll
        for (int kq = 0; kq < 8; kq++) {
            int kk = kg * 8 + kq;
            float av[TB];
            if constexpr (TB == 4) {
                float4 a4 = *(const float4*)&As[kk * ASTR + tcol * 4];
                av[0] = a4.x; av[1] = a4.y; av[2] = a4.z; av[3] = a4.w;
            } else {
                float2 a2 = *(const float2*)&As[kk * ASTR + tcol * 2];
                av[0] = a2.x; av[1] = a2.y;
            }
            float wv[TR];
#pragma unroll
            for (int i = 0; i < TR; i++) wv[i] = Ws[(trow * TR + i) * 33 + kk];
#pragma unroll
            for (int i = 0; i < TR; i++)
#pragma unroll
                for (int j = 0; j < TB; j++)
                    acc[i * TB + j] += wv[i] * av[j];
        }
        __syncthreads();
    }
}

// ---------------- persistent decoder: 128 blocks x 512 threads ----------------
__global__ __launch_bounds__(512) void dec_scan(
    const int* __restrict__ src, const float* __restrict__ XP,
    const float* __restrict__ ENC,
    const float* __restrict__ Wq, const float* __restrict__ bq,
    const float* __restrict__ dWih0, const float* __restrict__ dWhh0,
    const float* __restrict__ dWih1, const float* __restrict__ dWhh1,
    const float* __restrict__ B1,
    const float* __restrict__ Wout, const float* __restrict__ bout,
    float* __restrict__ D0HT, float* __restrict__ D1HT,
    float* __restrict__ D0CT, float* __restrict__ D1CT,
    float* __restrict__ Q, float* __restrict__ CTXT,
    float* __restrict__ out, unsigned* __restrict__ bar)
{
    __shared__ __align__(16) float SM[9232];
    float* As = SM;                  // up to 32*36 = 1152
    float* Ws = SM + 1152;           // up to 64*33 = 2112
    // sgred aliases SM[0..9215] (used only after GEMM loop + sync)
    float* qs = SM;                  // attention: 1024
    float* ec = SM + 1024;           // attention: 8*1024
    float* ssc = SM + 9216;          // attention: 8

    const int g = blockIdx.x;
    const int tid = threadIdx.x;
    const int kg = tid >> 7, tt = tid & 127;
    const int trow = tt >> 3, tcol = tt & 7;
    const int lane = tid & 31, w = tid >> 5;
    // cell decomposition
    const int rg = g >> 2, bg = g & 3;
    // qproj decomposition
    const int rgA = g >> 2, bgA = g & 3;
    // logits decomposition
    const int vg = g >> 3, bgE = g & 7;
    unsigned nb = 0;
    const size_t NS = (size_t)CH * CB;

    for (int t = 0; t < CT; t++) {
        const int cur = t & 1, nxt = cur ^ 1;

        // ---- Phase A: Q = d1h @ Wq^T + bq ----
        {
            float acc[8] = {};
            mgx<32, 32, 0>(acc, D1HT + (size_t)cur * NS, bgA * 32,
                           Wq, CH, 0, rgA * 32, CH, As, Ws);
            __syncthreads();
#pragma unroll
            for (int i = 0; i < 2; i++)
                *(float4*)&SM[kg * 1152 + (trow * 2 + i) * 36 + tcol * 4] =
                    *(float4*)&acc[i * 4];
            __syncthreads();
#pragma unroll
            for (int u = 0; u < 2; u++) {
                int o = tid + 512 * u;
                int rp = o >> 5, bp = o & 31;
                float s = bq[rgA * 32 + rp];
#pragma unroll
                for (int k = 0; k < 4; k++) s += SM[k * 1152 + rp * 36 + bp];
                Q[(size_t)(bgA * 32 + bp) * CH2 + rgA * 32 + rp] = s;
            }
        }
        gbar(bar, (++nb) * 128u);

        // ---- Phase B: attention for batch row g; writes CTXT [k][b] ----
        {
            qs[tid] = __ldcg(Q + (size_t)g * CH2 + tid);
            qs[tid + 512] = __ldcg(Q + (size_t)g * CH2 + tid + 512);
            __syncthreads();
            float mrun = -INFINITY, zrun = 0.0f;
            float cacc[2] = {0.f, 0.f};
            const float* Eb = ENC + (size_t)g * CS * CH2;
            for (int s0 = 0; s0 < CS; s0 += 8) {
#pragma unroll
                for (int u = 0; u < 4; u++) {
                    int li = tid + 512 * u;
                    int si = li >> 8, kq = li & 255;
                    ((float4*)(ec + si * 1024))[kq] =
                        __ldg((const float4*)(Eb + (size_t)(s0 + si) * CH2) + kq);
                }
                __syncthreads();
                if (w < 8) {
                    float p = 0.0f;
#pragma unroll
                    for (int i = 0; i < 32; i++)
                        p += ec[w * 1024 + lane + 32 * i] * qs[lane + 32 * i];
                    for (int o = 16; o; o >>= 1) p += __shfl_xor_sync(0xffffffffu, p, o);
                    if (lane == 0)
                        ssc[w] = (src[(size_t)g * CS + s0 + w] != 0) ? p : -1e9f;
                }
                __syncthreads();
                float mc = ssc[0];
#pragma unroll
                for (int i = 1; i < 8; i++) mc = fmaxf(mc, ssc[i]);
                float mnew = fmaxf(mrun, mc);
                float r = expf(mrun - mnew);
                float p8[8];
                float zs = 0.0f;
#pragma unroll
                for (int i = 0; i < 8; i++) { p8[i] = expf(ssc[i] - mnew); zs += p8[i]; }
                zrun = zrun * r + zs;
#pragma unroll
                for (int u = 0; u < 2; u++) {
                    int k = tid + 512 * u;
                    float cv = cacc[u] * r;
#pragma unroll
                    for (int i = 0; i < 8; i++) cv += p8[i] * ec[i * 1024 + k];
                    cacc[u] = cv;
                }
                mrun = mnew;
                __syncthreads();
            }
            float inv = 1.0f / zrun;
#pragma unroll
            for (int u = 0; u < 2; u++)
                CTXT[(size_t)(tid + 512 * u) * CB + g] = cacc[u] * inv;
        }
        gbar(bar, (++nb) * 128u);

        // ---- Phase C: cell0 — rows (gate,jj) for j in [rg*16,+16), b in [bg*32,+32) ----
        {
            float acc[16] = {};
            mgx<64, 32, 1>(acc, CTXT, bg * 32, dWih0, CE + CH2, CE, rg * 16, CH2, As, Ws);
            mgx<64, 32, 1>(acc, D0HT + (size_t)cur * NS, bg * 32, dWhh0, CH, 0, rg * 16, CH, As, Ws);
            __syncthreads();
#pragma unroll
            for (int i = 0; i < 4; i++)
                *(float4*)&SM[kg * 2304 + (trow * 4 + i) * 36 + tcol * 4] =
                    *(float4*)&acc[i * 4];
            __syncthreads();
            {
                int jj = tid >> 5, bp = tid & 31;
                int j = rg * 16 + jj, b = bg * 32 + bp;
                const float* pre = XP + ((size_t)t * CB + b) * CH4;
                float gs[4];
#pragma unroll
                for (int gx = 0; gx < 4; gx++) {
                    float s = __ldg(pre + gx * CH + j);
#pragma unroll
                    for (int k = 0; k < 4; k++)
                        s += SM[k * 2304 + (gx * 16 + jj) * 36 + bp];
                    gs[gx] = s;
                }
                size_t ci = (size_t)j * CB + b;
                float c = sigf(gs[1]) * D0CT[ci] + sigf(gs[0]) * tanhf(gs[2]);
                D0CT[ci] = c;
                D0HT[(size_t)nxt * NS + ci] = sigf(gs[3]) * tanhf(c);
            }
            __syncthreads();
        }
        gbar(bar, (++nb) * 128u);

        // ---- Phase D: cell1 ----
        {
            float acc[16] = {};
            mgx<64, 32, 1>(acc, D0HT + (size_t)nxt * NS, bg * 32, dWih1, CH, 0, rg * 16, CH, As, Ws);
            mgx<64, 32, 1>(acc, D1HT + (size_t)cur * NS, bg * 32, dWhh1, CH, 0, rg * 16, CH, As, Ws);
            __syncthreads();
#pragma unroll
            for (int i = 0; i < 4; i++)
                *(float4*)&SM[kg * 2304 + (trow * 4 + i) * 36 + tcol * 4] =
                    *(float4*)&acc[i * 4];
            __syncthreads();
            {
                int jj = tid >> 5, bp = tid & 31;
                int j = rg * 16 + jj, b = bg * 32 + bp;
                float gs[4];
#pragma unroll
                for (int gx = 0; gx < 4; gx++) {
                    float s = __ldg(B1 + gx * CH + j);
#pragma unroll
                    for (int k = 0; k < 4; k++)
                        s += SM[k * 2304 + (gx * 16 + jj) * 36 + bp];
                    gs[gx] = s;
                }
                size_t ci = (size_t)j * CB + b;
                float c = sigf(gs[1]) * D1CT[ci] + sigf(gs[0]) * tanhf(gs[2]);
                D1CT[ci] = c;
                D1HT[(size_t)nxt * NS + ci] = sigf(gs[3]) * tanhf(c);
            }
            __syncthreads();
        }
        gbar(bar, (++nb) * 128u);

        // ---- Phase E: logits — v in [vg*32,+32), b in [bgE*16,+16) ----
        {
            float acc[4] = {};
            mgx<32, 16, 0>(acc, D1HT + (size_t)nxt * NS, bgE * 16,
                           Wout, CH, 0, vg * 32, CH, As, Ws);
            __syncthreads();
#pragma unroll
            for (int i = 0; i < 2; i++)
                *(float2*)&SM[kg * 640 + (trow * 2 + i) * 20 + tcol * 2] =
                    *(float2*)&acc[i * 2];
            __syncthreads();
            {
                int rp = tid >> 4, bp = tid & 15;
                float s = bout[vg * 32 + rp];
#pragma unroll
                for (int k = 0; k < 4; k++) s += SM[k * 640 + rp * 20 + bp];
                out[(size_t)(bgE * 16 + bp) * CT * CV + (size_t)t * CV + vg * 32 + rp] = s;
            }
            __syncthreads();
        }
        // no barrier: E and next-A only read D1HT[nxt] (fenced at bar after D)
    }
}

// ---------------- host orchestration ----------------
extern "C" void kernel_launch(void* const* d_in, const int* in_sizes, int n_in,
                              void* d_out, int out_size)
{
    const int*   src    = (const int*)d_in[0];
    const int*   din    = (const int*)d_in[1];
    const float* emb    = (const float*)d_in[2];
    const float* eWih0  = (const float*)d_in[3];
    const float* eWhh0  = (const float*)d_in[4];
    const float* ebih0  = (const float*)d_in[5];
    const float* ebhh0  = (const float*)d_in[6];
    const float* eWih1  = (const float*)d_in[7];
    const float* eWhh1  = (const float*)d_in[8];
    const float* ebih1  = (const float*)d_in[9];
    const float* ebhh1  = (const float*)d_in[10];
    const float* dWih0  = (const float*)d_in[11];
    const float* dWhh0  = (const float*)d_in[12];
    const float* dbih0  = (const float*)d_in[13];
    const float* dbhh0  = (const float*)d_in[14];
    const float* dWih1  = (const float*)d_in[15];
    const float* dWhh1  = (const float*)d_in[16];
    const float* dbih1  = (const float*)d_in[17];
    const float* dbhh1  = (const float*)d_in[18];
    const float* Wq     = (const float*)d_in[19];
    const float* bq     = (const float*)d_in[20];
    const float* Wout   = (const float*)d_in[21];
    const float* bout   = (const float*)d_in[22];
    float* out = (float*)d_out;

    float *XS, *DE, *XP, *Y0, *ENC, *HB, *SC, *D0H, *D1H, *D0C, *D1C, *CTXT, *Q, *B1;
    unsigned *barE, *barD;
    cudaGetSymbolAddress((void**)&XS,   g_XS);
    cudaGetSymbolAddress((void**)&DE,   g_DE);
    cudaGetSymbolAddress((void**)&XP,   g_XP);
    cudaGetSymbolAddress((void**)&Y0,   g_Y0);
    cudaGetSymbolAddress((void**)&ENC,  g_ENC);
    cudaGetSymbolAddress((void**)&HB,   g_HB);
    cudaGetSymbolAddress((void**)&SC,   g_SC);
    cudaGetSymbolAddress((void**)&D0H,  g_d0h);
    cudaGetSymbolAddress((void**)&D1H,  g_d1h);
    cudaGetSymbolAddress((void**)&D0C,  g_d0c);
    cudaGetSymbolAddress((void**)&D1C,  g_d1c);
    cudaGetSymbolAddress((void**)&CTXT, g_ctxT);
    cudaGetSymbolAddress((void**)&Q,    g_q);
    cudaGetSymbolAddress((void**)&B1,   g_b1);
    cudaGetSymbolAddress((void**)&barE, g_barE);
    cudaGetSymbolAddress((void**)&barD, g_barD);

    embed_k<<<1024, 256>>>(emb, src, CS, XS, (long)CS * CB * CE);
    embed_k<<<1024, 256>>>(emb, din, CT, DE, (long)CT * CB * CE);

    sgemm_bias<<<dim3(CH4 / 64, (CS * CB) / 128, 2), 256>>>(
        CS * CB, CH4, CE, XS, CE,
        eWih0, CE, 0, (long long)CH4 * CE,
        ebih0, ebhh0, CH4,
        XP, (long long)CH4, (long long)CS * CB * CH4);

    cudaMemsetAsync(HB, 0, sizeof(float) * 2 * 2 * CB * CH);
    cudaMemsetAsync(SC, 0, sizeof(float) * 2 * CB * CH);
    cudaMemsetAsync(barE, 0, sizeof(unsigned));
    enc_scan<<<dim3(16, 4, 2), 256>>>(0, XP, eWhh0, HB, SC, Y0, D0H, D0C, barE);

    sgemm_bias<<<dim3(CH4 / 64, (CS * CB) / 128, 2), 256>>>(
        CS * CB, CH4, CH2, Y0, CH2,
        eWih1, CH2, 0, (long long)CH4 * CH2,
        ebih1, ebhh1, CH4,
        XP, (long long)CH4, (long long)CS * CB * CH4);

    cudaMemsetAsync(HB, 0, sizeof(float) * 2 * 2 * CB * CH);
    cudaMemsetAsync(SC, 0, sizeof(float) * 2 * CB * CH);
    cudaMemsetAsync(barE, 0, sizeof(unsigned));
    enc_scan<<<dim3(16, 4, 2), 256>>>(1, XP, eWhh1, HB, SC, ENC, D1H, D1C, barE);

    sgemm_bias<<<dim3(CH4 / 64, (CT * CB) / 128, 1), 256>>>(
        CT * CB, CH4, CE, DE, CE,
        dWih0, CE + CH2, 0, 0,
        dbih0, dbhh0, 0,
        XP, (long long)CH4, 0);

    vsum_k<<<(CH4 + 255) / 256, 256>>>(dbih1, dbhh1, B1, CH4);

    cudaMemsetAsync(barD, 0, sizeof(unsigned));
    dec_scan<<<128, 512>>>(src, XP, ENC, Wq, bq,
                           dWih0, dWhh0, dWih1, dWhh1, B1, Wout, bout,
                           D0H, D1H, D0C, D1C, Q, CTXT, out, barD);
}

// round 8
// speedup vs baseline: 1.7529x; 1.0450x over previous
#include <cuda_runtime.h>
#include <math.h>

#define CB 128
#define CS 256
#define CT 256
#define CV 512
#define CE 256
#define CH 512
#define CH2 1024
#define CH4 2048

// ---------------- static device scratch ----------------
static __device__ float g_XS[(size_t)CS * CB * CE];
static __device__ float g_DE[(size_t)CT * CB * CE];
static __device__ float g_XP[(size_t)2 * CS * CB * CH4];
static __device__ float g_Y0[(size_t)CS * CB * CH2];
static __device__ float g_ENC[(size_t)CB * CS * CH2];
static __device__ float g_HB[(size_t)2 * 2 * CB * CH];   // [buf][dir][b][j]
static __device__ float g_SC[(size_t)2 * CB * CH];       // [dir][b][j]
static __device__ float g_d0h[(size_t)2 * CH * CB];      // transposed [buf][j][b]
static __device__ float g_d1h[(size_t)2 * CH * CB];
static __device__ float g_d0c[(size_t)CH * CB];
static __device__ float g_d1c[(size_t)CH * CB];
static __device__ float g_ctxT[(size_t)CH2 * CB];        // transposed [k][b]
static __device__ float g_q[(size_t)CB * CH2];
static __device__ float g_b1[CH4];
static __device__ unsigned g_barE;
static __device__ unsigned g_barD;

// ---------------- grid barrier (all blocks resident) ----------------
__device__ __forceinline__ void gbar(unsigned* ctr, unsigned target)
{
    __syncthreads();
    if (threadIdx.x == 0) {
        __threadfence();
        atomicAdd(ctr, 1u);
        volatile unsigned* v = ctr;
        while (*v < target) __nanosleep(32);
    }
    __syncthreads();
}

__device__ __forceinline__ float sigf(float x) { return 1.0f / (1.0f + expf(-x)); }

// ---------------- tf32 helpers ----------------
__device__ __forceinline__ unsigned f2tf(float x)
{
    unsigned r;
    asm("cvt.rna.tf32.f32 %0, %1;" : "=r"(r) : "f"(x));
    return r;
}
__device__ __forceinline__ uint4 f2tf4(float4 v)
{
    uint4 u;
    u.x = f2tf(v.x); u.y = f2tf(v.y); u.z = f2tf(v.z); u.w = f2tf(v.w);
    return u;
}
__device__ __forceinline__ void mma_tf32(float* c, const unsigned* a, const unsigned* b)
{
    asm("mma.sync.aligned.m16n8k8.row.col.f32.tf32.tf32.f32 "
        "{%0,%1,%2,%3},{%4,%5,%6,%7},{%8,%9},{%0,%1,%2,%3};"
        : "+f"(c[0]), "+f"(c[1]), "+f"(c[2]), "+f"(c[3])
        : "r"(a[0]), "r"(a[1]), "r"(a[2]), "r"(a[3]), "r"(b[0]), "r"(b[1]));
}

// ---------------- embedding ----------------
__global__ void embed_k(const float* __restrict__ emb, const int* __restrict__ toks,
                        int L, float* __restrict__ X, long total)
{
    for (long i = (long)blockIdx.x * blockDim.x + threadIdx.x; i < total;
         i += (long)gridDim.x * blockDim.x) {
        int e = (int)(i % CE);
        long r = i / CE;
        int b = (int)(r % CB);
        int t = (int)(r / CB);
        int tok = toks[(long)b * L + t];
        X[i] = (tok == 0) ? 0.0f : emb[(long)tok * CE + e];
    }
}

// ---------------- precompute GEMM (tf32 tensor cores) ----------------
// C[z][M,N] = A[M,K] * W[z][N, woff..woff+K]^T + b0[z] + b1[z]
// block tile 128x64, 8 warps (4x2) of 32x32 warp tiles, K-chunk 32.
__global__ __launch_bounds__(256) void tgemm_bias(
    int M, int N, int K,
    const float* __restrict__ A, int lda,
    const float* __restrict__ W, int ldw, int woff, long long wstride,
    const float* __restrict__ b0, const float* __restrict__ b1, int bstride,
    float* __restrict__ C, long long ldc, long long cstride)
{
    __shared__ __align__(16) unsigned As[128 * 36];
    __shared__ __align__(16) unsigned Ws[64 * 36];
    const int z = blockIdx.z;
    W += (size_t)z * wstride;
    C += (size_t)z * cstride;
    const float* bb0 = b0 ? (b0 + (size_t)z * bstride) : 0;
    const float* bb1 = b1 ? (b1 + (size_t)z * bstride) : 0;

    const int bm = blockIdx.y * 128, bn = blockIdx.x * 64;
    const int tid = threadIdx.x;
    const int lane = tid & 31, w = tid >> 5;
    const int wm = (w & 3) * 32, wn = (w >> 2) * 32;
    const int grp = lane >> 2, tig = lane & 3;

    // loaders
    const int am = tid >> 1, ak = (tid & 1) * 16;     // A: 2 thr/row, 4 float4 each
    const int wr = tid >> 2, wkq = (tid & 3) * 8;     // W: 4 thr/row, 2 float4 each

    float4 av[4], wv[2];
#pragma unroll
    for (int j = 0; j < 4; j++)
        av[j] = *(const float4*)(A + (size_t)(bm + am) * lda + ak + 4 * j);
#pragma unroll
    for (int j = 0; j < 2; j++)
        wv[j] = *(const float4*)(W + (size_t)(bn + wr) * ldw + woff + wkq + 4 * j);

    float acc[2][4][4] = {};
    for (int k0 = 0; k0 < K; k0 += 32) {
#pragma unroll
        for (int j = 0; j < 4; j++)
            *(uint4*)&As[am * 36 + ak + 4 * j] = f2tf4(av[j]);
#pragma unroll
        for (int j = 0; j < 2; j++)
            *(uint4*)&Ws[wr * 36 + wkq + 4 * j] = f2tf4(wv[j]);
        __syncthreads();
        if (k0 + 32 < K) {
#pragma unroll
            for (int j = 0; j < 4; j++)
                av[j] = *(const float4*)(A + (size_t)(bm + am) * lda + k0 + 32 + ak + 4 * j);
#pragma unroll
            for (int j = 0; j < 2; j++)
                wv[j] = *(const float4*)(W + (size_t)(bn + wr) * ldw + woff + k0 + 32 + wkq + 4 * j);
        }
#pragma unroll
        for (int ks = 0; ks < 32; ks += 8) {
            unsigned af[2][4], bf[4][2];
#pragma unroll
            for (int mt = 0; mt < 2; mt++) {
                int r0 = wm + mt * 16 + grp;
                af[mt][0] = As[r0 * 36 + ks + tig];
                af[mt][1] = As[(r0 + 8) * 36 + ks + tig];
                af[mt][2] = As[r0 * 36 + ks + tig + 4];
                af[mt][3] = As[(r0 + 8) * 36 + ks + tig + 4];
            }
#pragma unroll
            for (int nt = 0; nt < 4; nt++) {
                int n0 = wn + nt * 8 + grp;
                bf[nt][0] = Ws[n0 * 36 + ks + tig];
                bf[nt][1] = Ws[n0 * 36 + ks + tig + 4];
            }
#pragma unroll
            for (int mt = 0; mt < 2; mt++)
#pragma unroll
                for (int nt = 0; nt < 4; nt++)
                    mma_tf32(acc[mt][nt], af[mt], bf[nt]);
        }
        __syncthreads();
    }
    // epilogue: c0 (grp, tig*2), c1 (+1), c2 (grp+8, tig*2), c3 (+1)
#pragma unroll
    for (int mt = 0; mt < 2; mt++) {
#pragma unroll
        for (int nt = 0; nt < 4; nt++) {
            int row = bm + wm + mt * 16 + grp;
            int col = bn + wn + nt * 8 + tig * 2;
            float bv0 = (bb0 ? bb0[col] : 0.0f) + (bb1 ? bb1[col] : 0.0f);
            float bv1 = (bb0 ? bb0[col + 1] : 0.0f) + (bb1 ? bb1[col + 1] : 0.0f);
            float2 o0 = {acc[mt][nt][0] + bv0, acc[mt][nt][1] + bv1};
            float2 o1 = {acc[mt][nt][2] + bv0, acc[mt][nt][3] + bv1};
            *(float2*)(C + (long long)row * ldc + col) = o0;
            *(float2*)(C + (long long)(row + 8) * ldc + col) = o1;
        }
    }
}

__global__ void vsum_k(const float* __restrict__ a, const float* __restrict__ b,
                       float* __restrict__ o, int n)
{
    int i = blockIdx.x * blockDim.x + threadIdx.x;
    if (i < n) o[i] = a[i] + b[i];
}

// ---------------- persistent encoder scan (unchanged) ----------------
__global__ __launch_bounds__(256) void enc_scan(
    int layer, const float* __restrict__ XP, const float* __restrict__ Whh,
    float* __restrict__ HB, float* __restrict__ SC, float* __restrict__ Yout,
    float* __restrict__ DHT, float* __restrict__ DCT, unsigned* __restrict__ bar)
{
    __shared__ float hs[32][33];
    __shared__ float ws[4][32][33];
    const int d = blockIdx.z;
    const int j0 = blockIdx.x * 32, b0 = blockIdx.y * 32;
    const int tid = threadIdx.x;
    const int jj = tid & 15, bb = tid >> 4;
    const float* W_d = Whh + (size_t)d * CH4 * CH;
    const int hk = tid & 31, hb = tid >> 5;
    const int wk = tid & 31, wr0 = tid >> 5;

    for (int t = 0; t < CS; t++) {
        const int td = d ? (CS - 1 - t) : t;
        const float* hin = HB + (size_t)(((t & 1) * 2 + d) * CB) * CH;
        float* hout = HB + (size_t)((((t + 1) & 1) * 2 + d) * CB) * CH;

        float acc[4][2][2] = {};
        float hr[4], wreg[16];
#pragma unroll
        for (int u = 0; u < 4; u++)
            hr[u] = __ldcg(hin + (size_t)(b0 + hb + 8 * u) * CH + hk);
#pragma unroll
        for (int u = 0; u < 16; u++) {
            int row = wr0 + 8 * u;
            int g = row >> 5, j = row & 31;
            wreg[u] = W_d[(size_t)(g * CH + j0 + j) * CH + wk];
        }
        for (int k0 = 0; k0 < CH; k0 += 32) {
#pragma unroll
            for (int u = 0; u < 4; u++) hs[hk][hb + 8 * u] = hr[u];
#pragma unroll
            for (int u = 0; u < 16; u++) {
                int row = wr0 + 8 * u;
                int g = row >> 5, j = row & 31;
                ws[g][wk][j] = wreg[u];
            }
            __syncthreads();
            if (k0 + 32 < CH) {
#pragma unroll
                for (int u = 0; u < 4; u++)
                    hr[u] = __ldcg(hin + (size_t)(b0 + hb + 8 * u) * CH + k0 + 32 + hk);
#pragma unroll
                for (int u = 0; u < 16; u++) {
                    int row = wr0 + 8 * u;
                    int g = row >> 5, j = row & 31;
                    wreg[u] = W_d[(size_t)(g * CH + j0 + j) * CH + k0 + 32 + wk];
                }
            }
#pragma unroll
            for (int kk = 0; kk < 32; kk++) {
                float h0 = hs[kk][bb], h1 = hs[kk][bb + 16];
#pragma unroll
                for (int g = 0; g < 4; g++) {
                    float w0 = ws[g][kk][jj], w1 = ws[g][kk][jj + 16];
                    acc[g][0][0] += h0 * w0;
                    acc[g][1][0] += h1 * w0;
                    acc[g][0][1] += h0 * w1;
                    acc[g][1][1] += h1 * w1;
                }
            }
            __syncthreads();
        }
        const float* pre = XP + ((size_t)d * CS + td) * CB * CH4;
#pragma unroll
        for (int bi = 0; bi < 2; bi++) {
            int b = b0 + bb + 16 * bi;
            const float* prow = pre + (size_t)b * CH4;
#pragma unroll
            for (int m = 0; m < 2; m++) {
                int j = j0 + jj + 16 * m;
                float gi = acc[0][bi][m] + prow[j];
                float gf = acc[1][bi][m] + prow[CH + j];
                float gg = acc[2][bi][m] + prow[2 * CH + j];
                float go = acc[3][bi][m] + prow[3 * CH + j];
                size_t ci = (size_t)(d * CB + b) * CH + j;
                float c = sigf(gf) * SC[ci] + sigf(gi) * tanhf(gg);
                SC[ci] = c;
                float h = sigf(go) * tanhf(c);
                hout[(size_t)b * CH + j] = h;
                size_t yi = (layer == 0)
                    ? ((size_t)td * CB + b) * CH2 + (size_t)d * CH + j
                    : ((size_t)b * CS + td) * CH2 + (size_t)d * CH + j;
                Yout[yi] = h;
            }
        }
        gbar(bar, (unsigned)(t + 1) * 128u);
    }
    if (d == 0) {
#pragma unroll
        for (int u = 0; u < 4; u++) {
            int li = tid + 256 * u;
            int j = li >> 5, b = li & 31;
            int gj = j0 + j, gb = b0 + b;
            float hf = __ldcg(HB + (size_t)(0 * CB + gb) * CH + gj);
            float hbv = __ldcg(HB + (size_t)(1 * CB + gb) * CH + gj);
            DHT[(size_t)gj * CB + gb] = hf + hbv;
            float cf = __ldcg(SC + (size_t)(0 * CB + gb) * CH + gj);
            float cbv = __ldcg(SC + (size_t)(CB + gb) * CH + gj);
            DCT[(size_t)gj * CB + gb] = cf + cbv;
        }
    }
}

// ---------------- decoder micro-GEMM: split-K, register tiles ----------------
template<int RPB, int BPB, int ROWMODE>
__device__ __forceinline__ void mgx(
    float* acc,
    const float* __restrict__ AT, int b0,
    const float* __restrict__ W, int ldw, int woff, int rbase, int K,
    float* __restrict__ As, float* __restrict__ Ws)
{
    constexpr int TR = RPB / 16, TB = BPB / 8;
    constexpr int ASTR = BPB + 4;
    constexpr int NA = (32 * BPB) / 512;
    constexpr int NW = (32 * RPB) / 512;
    const int tid = threadIdx.x;
    const int kg = tid >> 7, t = tid & 127;
    const int trow = t >> 3, tcol = t & 7;

    int wrow[NW];
#pragma unroll
    for (int u = 0; u < NW; u++) {
        int rp = (tid + 512 * u) >> 5;
        wrow[u] = (ROWMODE == 0) ? (rbase + rp)
                                 : ((rp >> 4) * CH + rbase + (rp & 15));
    }
    float areg[NA], wreg[NW];
#pragma unroll
    for (int u = 0; u < NA; u++) {
        int idx = tid + 512 * u;
        int k = idx / BPB, bp = idx % BPB;
        areg[u] = __ldcg(AT + (size_t)k * 128 + b0 + bp);
    }
#pragma unroll
    for (int u = 0; u < NW; u++) {
        int k = (tid + 512 * u) & 31;
        wreg[u] = __ldg(W + (size_t)wrow[u] * ldw + woff + k);
    }
    for (int k0 = 0; k0 < K; k0 += 32) {
#pragma unroll
        for (int u = 0; u < NA; u++) {
            int idx = tid + 512 * u;
            int k = idx / BPB, bp = idx % BPB;
            As[k * ASTR + bp] = areg[u];
        }
#pragma unroll
        for (int u = 0; u < NW; u++) {
            int idx = tid + 512 * u;
            Ws[(idx >> 5) * 33 + (idx & 31)] = wreg[u];
        }
        __syncthreads();
        if (k0 + 32 < K) {
#pragma unroll
            for (int u = 0; u < NA; u++) {
                int idx = tid + 512 * u;
                int k = idx / BPB, bp = idx % BPB;
                areg[u] = __ldcg(AT + (size_t)(k0 + 32 + k) * 128 + b0 + bp);
            }
#pragma unroll
            for (int u = 0; u < NW; u++) {
                int k = (tid + 512 * u) & 31;
                wreg[u] = __ldg(W + (size_t)wrow[u] * ldw + woff + k0 + 32 + k);
            }
        }
#pragma unroll
        for (int kq = 0; kq < 8; kq++) {
            int kk = kg * 8 + kq;
            float av[TB];
            if constexpr (TB == 4) {
                float4 a4 = *(const float4*)&As[kk * ASTR + tcol * 4];
                av[0] = a4.x; av[1] = a4.y; av[2] = a4.z; av[3] = a4.w;
            } else {
                float2 a2 = *(const float2*)&As[kk * ASTR + tcol * 2];
                av[0] = a2.x; av[1] = a2.y;
            }
            float wv[TR];
#pragma unroll
            for (int i = 0; i < TR; i++) wv[i] = Ws[(trow * TR + i) * 33 + kk];
#pragma unroll
            for (int i = 0; i < TR; i++)
#pragma unroll
                for (int j = 0; j < TB; j++)
                    acc[i * TB + j] += wv[i] * av[j];
        }
        __syncthreads();
    }
}

// ---------------- persistent decoder: 128 blocks x 512 threads ----------------
__global__ __launch_bounds__(512) void dec_scan(
    const int* __restrict__ src, const float* __restrict__ XP,
    const float* __restrict__ ENC,
    const float* __restrict__ Wq, const float* __restrict__ bq,
    const float* __restrict__ dWih0, const float* __restrict__ dWhh0,
    const float* __restrict__ dWih1, const float* __restrict__ dWhh1,
    const float* __restrict__ B1,
    const float* __restrict__ Wout, const float* __restrict__ bout,
    float* __restrict__ D0HT, float* __restrict__ D1HT,
    float* __restrict__ D0CT, float* __restrict__ D1CT,
    float* __restrict__ Q, float* __restrict__ CTXT,
    float* __restrict__ out, unsigned* __restrict__ bar)
{
    __shared__ __align__(16) float SM[9232];
    float* As = SM;
    float* Ws = SM + 1152;
    float* qs = SM;
    float* ec = SM + 1024;
    float* ssc = SM + 9216;

    const int g = blockIdx.x;
    const int tid = threadIdx.x;
    const int kg = tid >> 7, tt = tid & 127;
    const int trow = tt >> 3, tcol = tt & 7;
    const int lane = tid & 31, w = tid >> 5;
    const int rg = g >> 2, bg = g & 3;
    const int rgA = g >> 2, bgA = g & 3;
    const int vg = g >> 3, bgE = g & 7;
    unsigned nb = 0;
    const size_t NS = (size_t)CH * CB;

    for (int t = 0; t < CT; t++) {
        const int cur = t & 1, nxt = cur ^ 1;

        // ---- Phase A: Q = d1h @ Wq^T + bq ----
        {
            float acc[8] = {};
            mgx<32, 32, 0>(acc, D1HT + (size_t)cur * NS, bgA * 32,
                           Wq, CH, 0, rgA * 32, CH, As, Ws);
            __syncthreads();
#pragma unroll
            for (int i = 0; i < 2; i++)
                *(float4*)&SM[kg * 1152 + (trow * 2 + i) * 36 + tcol * 4] =
                    *(float4*)&acc[i * 4];
            __syncthreads();
#pragma unroll
            for (int u = 0; u < 2; u++) {
                int o = tid + 512 * u;
                int rp = o >> 5, bp = o & 31;
                float s = bq[rgA * 32 + rp];
#pragma unroll
                for (int k = 0; k < 4; k++) s += SM[k * 1152 + rp * 36 + bp];
                Q[(size_t)(bgA * 32 + bp) * CH2 + rgA * 32 + rp] = s;
            }
        }
        gbar(bar, (++nb) * 128u);

        // ---- Phase B: attention for batch row g; writes CTXT [k][b] ----
        {
            qs[tid] = __ldcg(Q + (size_t)g * CH2 + tid);
            qs[tid + 512] = __ldcg(Q + (size_t)g * CH2 + tid + 512);
            __syncthreads();
            float mrun = -INFINITY, zrun = 0.0f;
            float cacc[2] = {0.f, 0.f};
            const float* Eb = ENC + (size_t)g * CS * CH2;
            for (int s0 = 0; s0 < CS; s0 += 8) {
#pragma unroll
                for (int u = 0; u < 4; u++) {
                    int li = tid + 512 * u;
                    int si = li >> 8, kq = li & 255;
                    ((float4*)(ec + si * 1024))[kq] =
                        __ldg((const float4*)(Eb + (size_t)(s0 + si) * CH2) + kq);
                }
                __syncthreads();
                if (w < 8) {
                    float p = 0.0f;
#pragma unroll
                    for (int i = 0; i < 32; i++)
                        p += ec[w * 1024 + lane + 32 * i] * qs[lane + 32 * i];
                    for (int o = 16; o; o >>= 1) p += __shfl_xor_sync(0xffffffffu, p, o);
                    if (lane == 0)
                        ssc[w] = (src[(size_t)g * CS + s0 + w] != 0) ? p : -1e9f;
                }
                __syncthreads();
                float mc = ssc[0];
#pragma unroll
                for (int i = 1; i < 8; i++) mc = fmaxf(mc, ssc[i]);
                float mnew = fmaxf(mrun, mc);
                float r = expf(mrun - mnew);
                float p8[8];
                float zs = 0.0f;
#pragma unroll
                for (int i = 0; i < 8; i++) { p8[i] = expf(ssc[i] - mnew); zs += p8[i]; }
                zrun = zrun * r + zs;
#pragma unroll
                for (int u = 0; u < 2; u++) {
                    int k = tid + 512 * u;
                    float cv = cacc[u] * r;
#pragma unroll
                    for (int i = 0; i < 8; i++) cv += p8[i] * ec[i * 1024 + k];
                    cacc[u] = cv;
                }
                mrun = mnew;
                __syncthreads();
            }
            float inv = 1.0f / zrun;
#pragma unroll
            for (int u = 0; u < 2; u++)
                CTXT[(size_t)(tid + 512 * u) * CB + g] = cacc[u] * inv;
        }
        gbar(bar, (++nb) * 128u);

        // ---- Phase C: cell0 ----
        {
            float acc[16] = {};
            mgx<64, 32, 1>(acc, CTXT, bg * 32, dWih0, CE + CH2, CE, rg * 16, CH2, As, Ws);
            mgx<64, 32, 1>(acc, D0HT + (size_t)cur * NS, bg * 32, dWhh0, CH, 0, rg * 16, CH, As, Ws);
            __syncthreads();
#pragma unroll
            for (int i = 0; i < 4; i++)
                *(float4*)&SM[kg * 2304 + (trow * 4 + i) * 36 + tcol * 4] =
                    *(float4*)&acc[i * 4];
            __syncthreads();
            {
                int jj = tid >> 5, bp = tid & 31;
                int j = rg * 16 + jj, b = bg * 32 + bp;
                const float* pre = XP + ((size_t)t * CB + b) * CH4;
                float gs[4];
#pragma unroll
                for (int gx = 0; gx < 4; gx++) {
                    float s = __ldg(pre + gx * CH + j);
#pragma unroll
                    for (int k = 0; k < 4; k++)
                        s += SM[k * 2304 + (gx * 16 + jj) * 36 + bp];
                    gs[gx] = s;
                }
                size_t ci = (size_t)j * CB + b;
                float c = sigf(gs[1]) * D0CT[ci] + sigf(gs[0]) * tanhf(gs[2]);
                D0CT[ci] = c;
                D0HT[(size_t)nxt * NS + ci] = sigf(gs[3]) * tanhf(c);
            }
            __syncthreads();
        }
        gbar(bar, (++nb) * 128u);

        // ---- Phase D: cell1 ----
        {
            float acc[16] = {};
            mgx<64, 32, 1>(acc, D0HT + (size_t)nxt * NS, bg * 32, dWih1, CH, 0, rg * 16, CH, As, Ws);
            mgx<64, 32, 1>(acc, D1HT + (size_t)cur * NS, bg * 32, dWhh1, CH, 0, rg * 16, CH, As, Ws);
            __syncthreads();
#pragma unroll
            for (int i = 0; i < 4; i++)
                *(float4*)&SM[kg * 2304 + (trow * 4 + i) * 36 + tcol * 4] =
                    *(float4*)&acc[i * 4];
            __syncthreads();
            {
                int jj = tid >> 5, bp = tid & 31;
                int j = rg * 16 + jj, b = bg * 32 + bp;
                float gs[4];
#pragma unroll
                for (int gx = 0; gx < 4; gx++) {
                    float s = __ldg(B1 + gx * CH + j);
#pragma unroll
                    for (int k = 0; k < 4; k++)
                        s += SM[k * 2304 + (gx * 16 + jj) * 36 + bp];
                    gs[gx] = s;
                }
                size_t ci = (size_t)j * CB + b;
                float c = sigf(gs[1]) * D1CT[ci] + sigf(gs[0]) * tanhf(gs[2]);
                D1CT[ci] = c;
                D1HT[(size_t)nxt * NS + ci] = sigf(gs[3]) * tanhf(c);
            }
            __syncthreads();
        }
        gbar(bar, (++nb) * 128u);

        // ---- Phase E: logits ----
        {
            float acc[4] = {};
            mgx<32, 16, 0>(acc, D1HT + (size_t)nxt * NS, bgE * 16,
                           Wout, CH, 0, vg * 32, CH, As, Ws);
            __syncthreads();
#pragma unroll
            for (int i = 0; i < 2; i++)
                *(float2*)&SM[kg * 640 + (trow * 2 + i) * 20 + tcol * 2] =
                    *(float2*)&acc[i * 2];
            __syncthreads();
            {
                int rp = tid >> 4, bp = tid & 15;
                float s = bout[vg * 32 + rp];
#pragma unroll
                for (int k = 0; k < 4; k++) s += SM[k * 640 + rp * 20 + bp];
                out[(size_t)(bgE * 16 + bp) * CT * CV + (size_t)t * CV + vg * 32 + rp] = s;
            }
            __syncthreads();
        }
    }
}

// ---------------- host orchestration ----------------
extern "C" void kernel_launch(void* const* d_in, const int* in_sizes, int n_in,
                              void* d_out, int out_size)
{
    const int*   src    = (const int*)d_in[0];
    const int*   din    = (const int*)d_in[1];
    const float* emb    = (const float*)d_in[2];
    const float* eWih0  = (const float*)d_in[3];
    const float* eWhh0  = (const float*)d_in[4];
    const float* ebih0  = (const float*)d_in[5];
    const float* ebhh0  = (const float*)d_in[6];
    const float* eWih1  = (const float*)d_in[7];
    const float* eWhh1  = (const float*)d_in[8];
    const float* ebih1  = (const float*)d_in[9];
    const float* ebhh1  = (const float*)d_in[10];
    const float* dWih0  = (const float*)d_in[11];
    const float* dWhh0  = (const float*)d_in[12];
    const float* dbih0  = (const float*)d_in[13];
    const float* dbhh0  = (const float*)d_in[14];
    const float* dWih1  = (const float*)d_in[15];
    const float* dWhh1  = (const float*)d_in[16];
    const float* dbih1  = (const float*)d_in[17];
    const float* dbhh1  = (const float*)d_in[18];
    const float* Wq     = (const float*)d_in[19];
    const float* bq     = (const float*)d_in[20];
    const float* Wout   = (const float*)d_in[21];
    const float* bout   = (const float*)d_in[22];
    float* out = (float*)d_out;

    float *XS, *DE, *XP, *Y0, *ENC, *HB, *SC, *D0H, *D1H, *D0C, *D1C, *CTXT, *Q, *B1;
    unsigned *barE, *barD;
    cudaGetSymbolAddress((void**)&XS,   g_XS);
    cudaGetSymbolAddress((void**)&DE,   g_DE);
    cudaGetSymbolAddress((void**)&XP,   g_XP);
    cudaGetSymbolAddress((void**)&Y0,   g_Y0);
    cudaGetSymbolAddress((void**)&ENC,  g_ENC);
    cudaGetSymbolAddress((void**)&HB,   g_HB);
    cudaGetSymbolAddress((void**)&SC,   g_SC);
    cudaGetSymbolAddress((void**)&D0H,  g_d0h);
    cudaGetSymbolAddress((void**)&D1H,  g_d1h);
    cudaGetSymbolAddress((void**)&D0C,  g_d0c);
    cudaGetSymbolAddress((void**)&D1C,  g_d1c);
    cudaGetSymbolAddress((void**)&CTXT, g_ctxT);
    cudaGetSymbolAddress((void**)&Q,    g_q);
    cudaGetSymbolAddress((void**)&B1,   g_b1);
    cudaGetSymbolAddress((void**)&barE, g_barE);
    cudaGetSymbolAddress((void**)&barD, g_barD);

    embed_k<<<1024, 256>>>(emb, src, CS, XS, (long)CS * CB * CE);
    embed_k<<<1024, 256>>>(emb, din, CT, DE, (long)CT * CB * CE);

    tgemm_bias<<<dim3(CH4 / 64, (CS * CB) / 128, 2), 256>>>(
        CS * CB, CH4, CE, XS, CE,
        eWih0, CE, 0, (long long)CH4 * CE,
        ebih0, ebhh0, CH4,
        XP, (long long)CH4, (long long)CS * CB * CH4);

    cudaMemsetAsync(HB, 0, sizeof(float) * 2 * 2 * CB * CH);
    cudaMemsetAsync(SC, 0, sizeof(float) * 2 * CB * CH);
    cudaMemsetAsync(barE, 0, sizeof(unsigned));
    enc_scan<<<dim3(16, 4, 2), 256>>>(0, XP, eWhh0, HB, SC, Y0, D0H, D0C, barE);

    tgemm_bias<<<dim3(CH4 / 64, (CS * CB) / 128, 2), 256>>>(
        CS * CB, CH4, CH2, Y0, CH2,
        eWih1, CH2, 0, (long long)CH4 * CH2,
        ebih1, ebhh1, CH4,
        XP, (long long)CH4, (long long)CS * CB * CH4);

    cudaMemsetAsync(HB, 0, sizeof(float) * 2 * 2 * CB * CH);
    cudaMemsetAsync(SC, 0, sizeof(float) * 2 * CB * CH);
    cudaMemsetAsync(barE, 0, sizeof(unsigned));
    enc_scan<<<dim3(16, 4, 2), 256>>>(1, XP, eWhh1, HB, SC, ENC, D1H, D1C, barE);

    tgemm_bias<<<dim3(CH4 / 64, (CT * CB) / 128, 1), 256>>>(
        CT * CB, CH4, CE, DE, CE,
        dWih0, CE + CH2, 0, 0,
        dbih0, dbhh0, 0,
        XP, (long long)CH4, 0);

    vsum_k<<<(CH4 + 255) / 256, 256>>>(dbih1, dbhh1, B1, CH4);

    cudaMemsetAsync(barD, 0, sizeof(unsigned));
    dec_scan<<<128, 512>>>(src, XP, ENC, Wq, bq,
                           dWih0, dWhh0, dWih1, dWhh1, B1, Wout, bout,
                           D0H, D1H, D0C, D1C, Q, CTXT, out, barD);
}